// round 13
// baseline (speedup 1.0000x reference)
#include <cuda_runtime.h>
#include <cuda_bf16.h>
#include <cstdint>
#include <math.h>

#define B_    2
#define L_    4096
#define D_    1024
#define C_    4
#define NFFT  8192          // conv length
#define N2    4096          // complex FFT length (real-packed)
#define LOG2N2 12
#define CD_   (C_*D_)

// XOR swizzle (bijective on [0,4096)); conflict-free for butterflies AND
// for the bit-reversed scatter writes.
#define SWZ(i) ((i) ^ (((i) >> 4) & 15) ^ (((i) >> 8) & 15))
#define BREV(i) ((int)(__brev((unsigned)(i)) >> 20))

// -------- scratch (device globals: allocation-free) --------
__device__ __align__(128) float  g_xt[B_*D_*L_];        // x transposed [b][d][l]
__device__ __align__(128) float2 g_Xf[B_*D_*N2];        // packed rfft of x rows
__device__ __align__(128) float2 g_Kf[C_*D_*N2];        // packed rfft of kernel rows
__device__ __align__(128) float2 g_tw[NFFT/2];          // e^{-2pi i k/8192}
// bf16 split conv output, [b][cd][l] (K-as-rows for trans-ldmatrix A)
__device__ __align__(128) __nv_bfloat16 g_yh[(size_t)B_*CD_*L_];
__device__ __align__(128) __nv_bfloat16 g_yl[(size_t)B_*CD_*L_];
// bf16 split operands for tensor-core GEMMs
__device__ __align__(128) __nv_bfloat16 g_wt_hi[D_*CD_];             // out_w^T [j][cd]
__device__ __align__(128) __nv_bfloat16 g_wt_lo[D_*CD_];
__device__ __align__(128) __nv_bfloat16 g_ut_hi[(size_t)B_*L_*D_];   // u split [b*L+l][d]
__device__ __align__(128) __nv_bfloat16 g_ut_lo[(size_t)B_*L_*D_];
__device__ __align__(128) __nv_bfloat16 g_w2_hi[D_*D_];              // in_w^T [n][k]
__device__ __align__(128) __nv_bfloat16 g_w2_lo[D_*D_];

// single dynamic smem symbol shared by all kernels
extern __shared__ char dynsmem[];

// -------- twiddle table --------
__global__ void k_tw() {
    int k = blockIdx.x*blockDim.x + threadIdx.x;
    if (k < NFFT/2) {
        double a = -2.0*M_PI*(double)k/(double)NFFT;
        g_tw[k] = make_float2((float)cos(a), (float)sin(a));
    }
}

// -------- split u into bf16 hi/lo (already K-major) --------
__global__ __launch_bounds__(256) void k_usplit(const float* __restrict__ u) {
    size_t e = ((size_t)blockIdx.x*blockDim.x + threadIdx.x)*2;
    float2 v = *(const float2*)&u[e];
    __nv_bfloat16 h0 = __float2bfloat16(v.x);
    __nv_bfloat16 h1 = __float2bfloat16(v.y);
    __nv_bfloat16 l0 = __float2bfloat16(v.x - __bfloat162float(h0));
    __nv_bfloat16 l1 = __float2bfloat16(v.y - __bfloat162float(h1));
    __nv_bfloat162 hh; hh.x = h0; hh.y = h1;
    __nv_bfloat162 ll; ll.x = l0; ll.y = l1;
    *(__nv_bfloat162*)&g_ut_hi[e] = hh;
    *(__nv_bfloat162*)&g_ut_lo[e] = ll;
}

// -------- transpose + split in_w [k][n] -> [n][k] --------
__global__ __launch_bounds__(256) void k_w2tr(const float* __restrict__ inw) {
    __shared__ float t[32][33];
    int k0 = blockIdx.x*32, j0 = blockIdx.y*32;
    int tx = threadIdx.x, ty = threadIdx.y;
#pragma unroll
    for (int r = 0; r < 32; r += 8)
        t[ty+r][tx] = inw[(size_t)(k0+ty+r)*D_ + j0+tx];
    __syncthreads();
#pragma unroll
    for (int r = 0; r < 32; r += 8) {
        float v = t[tx][ty+r];
        __nv_bfloat16 h = __float2bfloat16(v);
        __nv_bfloat16 lo = __float2bfloat16(v - __bfloat162float(h));
        size_t o = (size_t)(j0+ty+r)*D_ + k0+tx;
        g_w2_hi[o] = h; g_w2_lo[o] = lo;
    }
}

// -------- transpose + split out_w [cd][j] -> [j][cd] --------
__global__ __launch_bounds__(256) void k_wtr(const float* __restrict__ outw) {
    __shared__ float t[32][33];
    int k0 = blockIdx.x*32, j0 = blockIdx.y*32;
    int tx = threadIdx.x, ty = threadIdx.y;
#pragma unroll
    for (int r = 0; r < 32; r += 8)
        t[ty+r][tx] = outw[(size_t)(k0+ty+r)*D_ + j0+tx];
    __syncthreads();
#pragma unroll
    for (int r = 0; r < 32; r += 8) {
        float v = t[tx][ty+r];
        __nv_bfloat16 h = __float2bfloat16(v);
        __nv_bfloat16 lo = __float2bfloat16(v - __bfloat162float(h));
        size_t o = (size_t)(j0+ty+r)*CD_ + k0+tx;
        g_wt_hi[o] = h; g_wt_lo[o] = lo;
    }
}

// ======== radix-8-fused FFT on N2=4096 complex points in shared ========
// Input must ALREADY be at bit-reversed (SWZ'd) positions; output natural.
__device__ __forceinline__ void bf2(float2& a, float2& b, float2 w, bool inv) {
    float wy = inv ? -w.y : w.y;
    float brx = b.x*w.x - b.y*wy;
    float bry = b.x*wy + b.y*w.x;
    b.x = a.x - brx; b.y = a.y - bry;
    a.x += brx;      a.y += bry;
}

// requires blockDim.x == 512; caller must __syncthreads() before calling
__device__ __forceinline__ void block_fft(float2* s, int tid, bool inv) {
#pragma unroll
    for (int sp = 0; sp < LOG2N2; sp += 3) {
        int half = 1 << sp;
        int pos  = tid & (half - 1);
        int base = ((tid >> sp) << (sp + 3)) | pos;
        float2 v[8];
#pragma unroll
        for (int q = 0; q < 8; ++q) v[q] = s[SWZ(base + q*half)];
        int stepA = NFFT >> (sp + 1);
        int stepB = NFFT >> (sp + 2);
        int stepC = NFFT >> (sp + 3);
        float2 wA = __ldg(&g_tw[pos*stepA]);
        bf2(v[0], v[1], wA, inv); bf2(v[2], v[3], wA, inv);
        bf2(v[4], v[5], wA, inv); bf2(v[6], v[7], wA, inv);
        float2 wB0 = __ldg(&g_tw[pos*stepB]), wB1 = __ldg(&g_tw[(pos+half)*stepB]);
        bf2(v[0], v[2], wB0, inv); bf2(v[1], v[3], wB1, inv);
        bf2(v[4], v[6], wB0, inv); bf2(v[5], v[7], wB1, inv);
        float2 wC0 = __ldg(&g_tw[pos*stepC]),        wC1 = __ldg(&g_tw[(pos+half)*stepC]);
        float2 wC2 = __ldg(&g_tw[(pos+2*half)*stepC]), wC3 = __ldg(&g_tw[(pos+3*half)*stepC]);
        bf2(v[0], v[4], wC0, inv); bf2(v[1], v[5], wC1, inv);
        bf2(v[2], v[6], wC2, inv); bf2(v[3], v[7], wC3, inv);
#pragma unroll
        for (int q = 0; q < 8; ++q) s[SWZ(base + q*half)] = v[q];
        __syncthreads();
    }
}

#define SMEM_FFT (N2 * (int)sizeof(float2))   // 32 KB data only

__device__ __forceinline__ float2 ldcs2(const float2* p) {
    float2 r;
    asm volatile("ld.global.cs.v2.f32 {%0,%1}, [%2];" : "=f"(r.x), "=f"(r.y) : "l"(p));
    return r;
}

// -------- forward rfft of real rows (load straight into brev positions) ----
__global__ __launch_bounds__(512) void k_fft_fwd(const float* __restrict__ kern, int mode) {
    float2* s = (float2*)dynsmem;
    int tid = threadIdx.x, bs = blockDim.x;
    size_t row = blockIdx.x;
    const float* src = mode ? (kern + row*L_) : (g_xt + row*L_);
    for (int m = tid; m < N2; m += bs) {
        float2 v = (m < L_/2) ? ldcs2((const float2*)&src[2*m])
                              : make_float2(0.f, 0.f);
        s[SWZ(BREV(m))] = v;
    }
    __syncthreads();
    block_fft(s, tid, false);
    float2* dst = (mode ? g_Kf : g_Xf) + row*(size_t)N2;
    for (int k = tid; k < N2; k += bs) {
        if (k == 0) {
            float2 z0 = s[SWZ(0)];
            dst[0] = make_float2(z0.x + z0.y, z0.x - z0.y);
        } else {
            float2 A = s[SWZ(k)], Bm = s[SWZ(N2 - k)];
            float2 E = make_float2(0.5f*(A.x + Bm.x), 0.5f*(A.y - Bm.y));
            float2 O = make_float2(0.5f*(A.y + Bm.y), -0.5f*(A.x - Bm.x));
            float2 w = __ldg(&g_tw[k]);
            dst[k] = make_float2(E.x + w.x*O.x - w.y*O.y,
                                 E.y + w.x*O.y + w.y*O.x);
        }
    }
}

// ---- spectrum product (with dmat folded: K' = K + dsc) fused with inverse
// Hermitian pack (brev scatter) + inverse FFT + bf16 split epilogue ----
// block remap: d = idx>>3, bb = (idx&7)>>2, c = idx&3  (L2 reuse of xf/kf)
__global__ __launch_bounds__(512) void k_conv_ifft(const float* __restrict__ dmat) {
    float2* s = (float2*)dynsmem;
    int tid = threadIdx.x, bs = blockDim.x;
    int idx = blockIdx.x;
    int d   = idx >> 3;
    int sub = idx & 7;
    int bb  = sub >> 2;
    int c   = sub & 3;
    int cd  = c*D_ + d;
    const float2* __restrict__ xf = g_Xf + ((size_t)(bb*D_ + d))*N2;
    const float2* __restrict__ kf = g_Kf + (size_t)cd*N2;
    float dsc = __ldg(&dmat[cd]);
    for (int k = tid; k < N2/2; k += bs) {
        if (k == 0) {
            float2 a0 = __ldg(&xf[0]), b0 = __ldg(&kf[0]);
            float y0 = a0.x*(b0.x + dsc), yn = a0.y*(b0.y + dsc);
            s[SWZ(0)] = make_float2(0.5f*(y0 + yn), 0.5f*(y0 - yn));   // BREV(0)=0
            float2 ah = __ldg(&xf[N2/2]), bh = __ldg(&kf[N2/2]);
            bh.x += dsc;
            float2 Yh = make_float2(ah.x*bh.x - ah.y*bh.y, ah.x*bh.y + ah.y*bh.x);
            s[SWZ(1)] = make_float2(Yh.x, -Yh.y);                       // BREV(N2/2)=1
        } else {
            float2 a  = __ldg(&xf[k]),      b  = __ldg(&kf[k]);
            float2 a2 = __ldg(&xf[N2 - k]), b2 = __ldg(&kf[N2 - k]);
            b.x += dsc; b2.x += dsc;
            float2 Yk = make_float2(a.x*b.x - a.y*b.y,   a.x*b.y + a.y*b.x);
            float2 Ym = make_float2(a2.x*b2.x - a2.y*b2.y, a2.x*b2.y + a2.y*b2.x);
            float2 E  = make_float2(0.5f*(Yk.x + Ym.x), 0.5f*(Yk.y - Ym.y));
            float2 Ow = make_float2(0.5f*(Yk.x - Ym.x), 0.5f*(Yk.y + Ym.y));
            float2 w = __ldg(&g_tw[k]);
            float2 O = make_float2(Ow.x*w.x + Ow.y*w.y, Ow.y*w.x - Ow.x*w.y);
            s[SWZ(BREV(k))]      = make_float2(E.x - O.y,  E.y + O.x);
            s[SWZ(BREV(N2 - k))] = make_float2(E.x + O.y, -E.y + O.x);
        }
    }
    __syncthreads();
    block_fft(s, tid, true);
    size_t orow = (size_t)(bb*CD_ + cd)*L_;
    __nv_bfloat162* yh = (__nv_bfloat162*)(g_yh + orow);
    __nv_bfloat162* yl = (__nv_bfloat162*)(g_yl + orow);
    const float invn = 1.0f/(float)N2;
    for (int m = tid; m < L_/2; m += bs) {
        float2 z = s[SWZ(m)];
        float ox = z.x*invn;
        float oy = z.y*invn;
        __nv_bfloat16 h0 = __float2bfloat16(ox);
        __nv_bfloat16 h1 = __float2bfloat16(oy);
        __nv_bfloat16 l0 = __float2bfloat16(ox - __bfloat162float(h0));
        __nv_bfloat16 l1 = __float2bfloat16(oy - __bfloat162float(h1));
        __nv_bfloat162 hh; hh.x = h0; hh.y = h1;
        __nv_bfloat162 ll; ll.x = l0; ll.y = l1;
        yh[m] = hh;
        yl[m] = ll;
    }
}

// ======== mma.sync bf16 split GEMM machinery ========
#define KP 40   // smem row pitch (bf16): 32 data + 8 pad
#define BUFE (128*KP)            // elements per buffer
#define BUFB (BUFE*2)            // bytes per buffer
#define SM_MMA (2*4*BUFB)        // 2 stages x 4 buffers = 81920 B

__device__ __forceinline__ uint32_t smem_u32(const void* p) {
    uint32_t a;
    asm("{ .reg .u64 t; cvta.to.shared.u64 t, %1; cvt.u32.u64 %0, t; }" : "=r"(a) : "l"(p));
    return a;
}
__device__ __forceinline__ void cpa16(uint32_t saddr, const void* g) {
    asm volatile("cp.async.cg.shared.global [%0], [%1], 16;" :: "r"(saddr), "l"(g));
}
__device__ __forceinline__ void ldsm4(uint32_t& r0, uint32_t& r1, uint32_t& r2,
                                      uint32_t& r3, uint32_t addr) {
    asm volatile("ldmatrix.sync.aligned.m8n8.x4.shared.b16 {%0,%1,%2,%3}, [%4];"
                 : "=r"(r0), "=r"(r1), "=r"(r2), "=r"(r3) : "r"(addr));
}
__device__ __forceinline__ void ldsm4t(uint32_t& r0, uint32_t& r1, uint32_t& r2,
                                       uint32_t& r3, uint32_t addr) {
    asm volatile("ldmatrix.sync.aligned.m8n8.x4.trans.shared.b16 {%0,%1,%2,%3}, [%4];"
                 : "=r"(r0), "=r"(r1), "=r"(r2), "=r"(r3) : "r"(addr));
}
__device__ __forceinline__ void mma16816(float* d, const uint32_t* a, const uint32_t* b) {
    asm volatile(
        "mma.sync.aligned.m16n8k16.row.col.f32.bf16.bf16.f32 "
        "{%0,%1,%2,%3}, {%4,%5,%6,%7}, {%8,%9}, {%0,%1,%2,%3};"
        : "+f"(d[0]), "+f"(d[1]), "+f"(d[2]), "+f"(d[3])
        : "r"(a[0]), "r"(a[1]), "r"(a[2]), "r"(a[3]), "r"(b[0]), "r"(b[1]));
}

// ======== k_mma_in: in_proj GEMM (A row-major [m][k]) ======
__global__ __launch_bounds__(256) void k_mma_in(const float* __restrict__ bias) {
    const int KDIM = D_;
    uint32_t sbase = smem_u32(dynsmem);
    int tid = threadIdx.x, wid = tid >> 5, lid = tid & 31;
    int n0 = blockIdx.x*128, m0 = blockIdx.y*128;
    int wm = wid & 3, wn = wid >> 2;

    float acc[2][8][4];
#pragma unroll
    for (int i = 0; i < 2; ++i)
#pragma unroll
        for (int j = 0; j < 8; ++j)
#pragma unroll
            for (int c = 0; c < 4; ++c) acc[i][j][c] = 0.f;

    int r0i = tid >> 2, c0i = tid & 3;
    int r1i = r0i + 64;
    const __nv_bfloat16* pA0h = g_ut_hi + (size_t)(m0 + r0i)*KDIM + c0i*8;
    const __nv_bfloat16* pA1h = g_ut_hi + (size_t)(m0 + r1i)*KDIM + c0i*8;
    const __nv_bfloat16* pA0l = g_ut_lo + (size_t)(m0 + r0i)*KDIM + c0i*8;
    const __nv_bfloat16* pA1l = g_ut_lo + (size_t)(m0 + r1i)*KDIM + c0i*8;
    const __nv_bfloat16* pB0h = g_w2_hi + (size_t)(n0 + r0i)*KDIM + c0i*8;
    const __nv_bfloat16* pB1h = g_w2_hi + (size_t)(n0 + r1i)*KDIM + c0i*8;
    const __nv_bfloat16* pB0l = g_w2_lo + (size_t)(n0 + r0i)*KDIM + c0i*8;
    const __nv_bfloat16* pB1l = g_w2_lo + (size_t)(n0 + r1i)*KDIM + c0i*8;
    uint32_t so0 = (r0i*KP + c0i*8)*2;
    uint32_t so1 = (r1i*KP + c0i*8)*2;

    const int NS = KDIM/32;

#define ISSUE_IN(s, stg) do {                                                 \
        int _k0 = (s)*32;                                                     \
        uint32_t _st = sbase + (stg)*4*BUFB;                                  \
        cpa16(_st + 0*BUFB + so0, pA0h + _k0);                                \
        cpa16(_st + 0*BUFB + so1, pA1h + _k0);                                \
        cpa16(_st + 1*BUFB + so0, pA0l + _k0);                                \
        cpa16(_st + 1*BUFB + so1, pA1l + _k0);                                \
        cpa16(_st + 2*BUFB + so0, pB0h + _k0);                                \
        cpa16(_st + 2*BUFB + so1, pB1h + _k0);                                \
        cpa16(_st + 3*BUFB + so0, pB0l + _k0);                                \
        cpa16(_st + 3*BUFB + so1, pB1l + _k0);                                \
        asm volatile("cp.async.commit_group;");                               \
    } while (0)

    ISSUE_IN(0, 0);

    for (int s = 0; s < NS; ++s) {
        if (s + 1 < NS) {
            ISSUE_IN(s + 1, (s + 1) & 1);
            asm volatile("cp.async.wait_group 1;");
        } else {
            asm volatile("cp.async.wait_group 0;");
        }
        __syncthreads();
        uint32_t soff = (uint32_t)(s & 1)*4*BUFB;
        uint32_t aAh = sbase + soff + 0*BUFB;
        uint32_t aAl = sbase + soff + 1*BUFB;
        uint32_t aBh = sbase + soff + 2*BUFB;
        uint32_t aBl = sbase + soff + 3*BUFB;
#pragma unroll
        for (int h = 0; h < 2; ++h) {
            int koff = h*16;
            uint32_t ah[2][4], al[2][4];
            {
                int mat = lid >> 3, rin = lid & 7;
                int arow = wm*32 + ((mat & 1) ? 8 : 0) + rin;
                int acol = koff + ((mat >> 1) ? 8 : 0);
#pragma unroll
                for (int mt = 0; mt < 2; ++mt) {
                    uint32_t off = ((arow + mt*16)*KP + acol)*2;
                    ldsm4(ah[mt][0], ah[mt][1], ah[mt][2], ah[mt][3], aAh + off);
                    ldsm4(al[mt][0], al[mt][1], al[mt][2], al[mt][3], aAl + off);
                }
            }
            {
                int mat = lid >> 3, rin = lid & 7;
                int bro = wn*64 + ((mat >> 1) ? 8 : 0) + rin;
                int bco = koff + ((mat & 1) ? 8 : 0);
#pragma unroll
                for (int jt2 = 0; jt2 < 4; ++jt2) {
                    uint32_t off = ((bro + jt2*16)*KP + bco)*2;
                    uint32_t bh[4], bl[4];
                    ldsm4(bh[0], bh[1], bh[2], bh[3], aBh + off);
                    ldsm4(bl[0], bl[1], bl[2], bl[3], aBl + off);
#pragma unroll
                    for (int mt = 0; mt < 2; ++mt) {
                        mma16816(acc[mt][jt2*2],   ah[mt], bh);
                        mma16816(acc[mt][jt2*2],   ah[mt], bl);
                        mma16816(acc[mt][jt2*2],   al[mt], bh);
                        mma16816(acc[mt][jt2*2+1], ah[mt], bh+2);
                        mma16816(acc[mt][jt2*2+1], ah[mt], bl+2);
                        mma16816(acc[mt][jt2*2+1], al[mt], bh+2);
                    }
                }
            }
        }
        __syncthreads();
    }
#undef ISSUE_IN

    int qr = lid >> 2, qc = lid & 3;
#pragma unroll
    for (int mt = 0; mt < 2; ++mt) {
#pragma unroll
        for (int jt = 0; jt < 8; ++jt) {
            int n = n0 + wn*64 + jt*8 + qc*2;
            int m_a = m0 + wm*32 + mt*16 + qr;
            int m_b = m_a + 8;
            float b0 = bias[n], b1 = bias[n+1];
            int ba = m_a >> 12, la = m_a & (L_-1);
            int bbv = m_b >> 12, lb = m_b & (L_-1);
            g_xt[((size_t)(ba*D_  + n  ))*L_ + la] = acc[mt][jt][0] + b0;
            g_xt[((size_t)(ba*D_  + n+1))*L_ + la] = acc[mt][jt][1] + b1;
            g_xt[((size_t)(bbv*D_ + n  ))*L_ + lb] = acc[mt][jt][2] + b0;
            g_xt[((size_t)(bbv*D_ + n+1))*L_ + lb] = acc[mt][jt][3] + b1;
        }
    }
}

// ======== k_mma_out: out_proj GEMM, A from [k][m] via ldmatrix.trans ========
#define KPA  136                 // A smem pitch (bf16): 128 data + 8 pad
#define ABUF (32*KPA*2)          // 8704 B per A buffer (32 k-rows x 128 m)
#define BBUF (128*KP*2)          // 10240 B per B buffer
#define STGB (2*ABUF + 2*BBUF)   // bytes per stage
#define SM_MO (2*STGB)           // 75776 B

__global__ __launch_bounds__(256) void k_mma_out(const float* __restrict__ outb,
                                                 float* __restrict__ out) {
    const int KDIM = CD_;
    uint32_t sbase = smem_u32(dynsmem);
    int tid = threadIdx.x, wid = tid >> 5, lid = tid & 31;
    int n0 = blockIdx.x*128, m0 = blockIdx.y*128;
    int wm = wid & 3, wn = wid >> 2;
    int bbm = m0 >> 12;                 // batch of this m-tile
    int l0  = m0 & (L_-1);

    float acc[2][8][4];
#pragma unroll
    for (int i = 0; i < 2; ++i)
#pragma unroll
        for (int j = 0; j < 8; ++j)
#pragma unroll
            for (int c = 0; c < 4; ++c) acc[i][j][c] = 0.f;

    // A: [k][m] rows; thread handles rows rA and rA+16, chunk cA
    int rA = tid >> 4, cA = tid & 15;
    const __nv_bfloat16* Ahb = g_yh + (size_t)bbm*CD_*L_ + l0;
    const __nv_bfloat16* Alb = g_yl + (size_t)bbm*CD_*L_ + l0;
    uint32_t soA0 = (rA*KPA + cA*8)*2;
    uint32_t soA1 = ((rA+16)*KPA + cA*8)*2;
    // B: [n][k] rows
    int r0i = tid >> 2, c0i = tid & 3;
    int r1i = r0i + 64;
    const __nv_bfloat16* pB0h = g_wt_hi + (size_t)(n0 + r0i)*KDIM + c0i*8;
    const __nv_bfloat16* pB1h = g_wt_hi + (size_t)(n0 + r1i)*KDIM + c0i*8;
    const __nv_bfloat16* pB0l = g_wt_lo + (size_t)(n0 + r0i)*KDIM + c0i*8;
    const __nv_bfloat16* pB1l = g_wt_lo + (size_t)(n0 + r1i)*KDIM + c0i*8;
    uint32_t soB0 = (r0i*KP + c0i*8)*2;
    uint32_t soB1 = (r1i*KP + c0i*8)*2;

    const int NS = KDIM/32;

#define ISSUE_OUT(s, stg) do {                                                \
        int _k0 = (s)*32;                                                     \
        uint32_t _st = sbase + (stg)*STGB;                                    \
        cpa16(_st + soA0,            Ahb + (size_t)(_k0 + rA)*L_ + cA*8);     \
        cpa16(_st + soA1,            Ahb + (size_t)(_k0 + rA + 16)*L_ + cA*8);\
        cpa16(_st + ABUF + soA0,     Alb + (size_t)(_k0 + rA)*L_ + cA*8);     \
        cpa16(_st + ABUF + soA1,     Alb + (size_t)(_k0 + rA + 16)*L_ + cA*8);\
        cpa16(_st + 2*ABUF + soB0,        pB0h + _k0);                        \
        cpa16(_st + 2*ABUF + soB1,        pB1h + _k0);                        \
        cpa16(_st + 2*ABUF + BBUF + soB0, pB0l + _k0);                        \
        cpa16(_st + 2*ABUF + BBUF + soB1, pB1l + _k0);                        \
        asm volatile("cp.async.commit_group;");                               \
    } while (0)

    ISSUE_OUT(0, 0);

    for (int s = 0; s < NS; ++s) {
        if (s + 1 < NS) {
            ISSUE_OUT(s + 1, (s + 1) & 1);
            asm volatile("cp.async.wait_group 1;");
        } else {
            asm volatile("cp.async.wait_group 0;");
        }
        __syncthreads();
        uint32_t soff = (uint32_t)(s & 1)*STGB;
        uint32_t aAh = sbase + soff;
        uint32_t aAl = sbase + soff + ABUF;
        uint32_t aBh = sbase + soff + 2*ABUF;
        uint32_t aBl = sbase + soff + 2*ABUF + BBUF;
#pragma unroll
        for (int h = 0; h < 2; ++h) {
            int koff = h*16;
            uint32_t ah[2][4], al[2][4];
            {
                int mat = lid >> 3, rin = lid & 7;
                int akrow = koff + ((mat >> 1) ? 8 : 0) + rin;
                int amcol = wm*32 + ((mat & 1) ? 8 : 0);
#pragma unroll
                for (int mt = 0; mt < 2; ++mt) {
                    uint32_t off = (akrow*KPA + amcol + mt*16)*2;
                    ldsm4t(ah[mt][0], ah[mt][1], ah[mt][2], ah[mt][3], aAh + off);
                    ldsm4t(al[mt][0], al[mt][1], al[mt][2], al[mt][3], aAl + off);
                }
            }
            {
                int mat = lid >> 3, rin = lid & 7;
                int bro = wn*64 + ((mat >> 1) ? 8 : 0) + rin;
                int bco = koff + ((mat & 1) ? 8 : 0);
#pragma unroll
                for (int jt2 = 0; jt2 < 4; ++jt2) {
                    uint32_t off = ((bro + jt2*16)*KP + bco)*2;
                    uint32_t bh[4], bl[4];
                    ldsm4(bh[0], bh[1], bh[2], bh[3], aBh + off);
                    ldsm4(bl[0], bl[1], bl[2], bl[3], aBl + off);
#pragma unroll
                    for (int mt = 0; mt < 2; ++mt) {
                        mma16816(acc[mt][jt2*2],   ah[mt], bh);
                        mma16816(acc[mt][jt2*2],   ah[mt], bl);
                        mma16816(acc[mt][jt2*2],   al[mt], bh);
                        mma16816(acc[mt][jt2*2+1], ah[mt], bh+2);
                        mma16816(acc[mt][jt2*2+1], ah[mt], bl+2);
                        mma16816(acc[mt][jt2*2+1], al[mt], bh+2);
                    }
                }
            }
        }
        __syncthreads();
    }
#undef ISSUE_OUT

    int qr = lid >> 2, qc = lid & 3;
#pragma unroll
    for (int mt = 0; mt < 2; ++mt) {
#pragma unroll
        for (int jt = 0; jt < 8; ++jt) {
            int n = n0 + wn*64 + jt*8 + qc*2;
            int m_a = m0 + wm*32 + mt*16 + qr;
            int m_b = m_a + 8;
            float b0 = outb[n], b1 = outb[n+1];
            int ba = m_a >> 12, la = m_a & (L_-1);
            int bbv = m_b >> 12, lb = m_b & (L_-1);
            float2 va = make_float2(acc[mt][jt][0] + b0, acc[mt][jt][1] + b1);
            float2 vb = make_float2(acc[mt][jt][2] + b0, acc[mt][jt][3] + b1);
            *(float2*)&out[((size_t)(ba*L_ + la))*D_ + n] = va;
            *(float2*)&out[((size_t)(bbv*L_ + lb))*D_ + n] = vb;
        }
    }
}

extern "C" void kernel_launch(void* const* d_in, const int* in_sizes, int n_in,
                              void* d_out, int out_size) {
    const float* u    = (const float*)d_in[0];
    const float* in_w = (const float*)d_in[1];
    const float* in_b = (const float*)d_in[2];
    const float* kern = (const float*)d_in[3];
    const float* dmat = (const float*)d_in[4];
    const float* outw = (const float*)d_in[5];
    const float* outb = (const float*)d_in[6];
    float* out = (float*)d_out;

    cudaFuncSetAttribute(k_fft_fwd,   cudaFuncAttributeMaxDynamicSharedMemorySize, SMEM_FFT);
    cudaFuncSetAttribute(k_conv_ifft, cudaFuncAttributeMaxDynamicSharedMemorySize, SMEM_FFT);
    cudaFuncSetAttribute(k_mma_out,   cudaFuncAttributeMaxDynamicSharedMemorySize, SM_MO);
    cudaFuncSetAttribute(k_mma_in,    cudaFuncAttributeMaxDynamicSharedMemorySize, SM_MMA);

    k_tw<<<(NFFT/2 + 255)/256, 256>>>();

    k_usplit<<<(B_*L_*D_/2)/256, 256>>>(u);
    { dim3 g(D_/32, D_/32);  k_w2tr<<<g, dim3(32,8)>>>(in_w); }
    { dim3 g(CD_/32, D_/32); k_wtr<<<g, dim3(32,8)>>>(outw); }

    { dim3 g(D_/128, (B_*L_)/128); k_mma_in<<<g, 256, SM_MMA>>>(in_b); }

    k_fft_fwd<<<B_*D_, 512, SMEM_FFT>>>(kern, 0);   // x rows
    k_fft_fwd<<<C_*D_, 512, SMEM_FFT>>>(kern, 1);   // kernel rows

    k_conv_ifft<<<B_*C_*D_, 512, SMEM_FFT>>>(dmat);

    { dim3 g(D_/128, (B_*L_)/128); k_mma_out<<<g, 256, SM_MO>>>(outb, out); }
}

// round 14
// speedup vs baseline: 1.0819x; 1.0819x over previous
#include <cuda_runtime.h>
#include <cuda_bf16.h>
#include <cstdint>
#include <math.h>

#define B_    2
#define L_    4096
#define D_    1024
#define C_    4
#define NFFT  8192          // conv length
#define N2    4096          // complex FFT length (real-packed)
#define LOG2N2 12
#define CD_   (C_*D_)

// XOR swizzle (bijective on [0,4096)); conflict-free for butterflies AND
// for the bit-reversed scatter writes.
#define SWZ(i) ((i) ^ (((i) >> 4) & 15) ^ (((i) >> 8) & 15))
#define BREV(i) ((int)(__brev((unsigned)(i)) >> 20))

// -------- scratch (device globals: allocation-free) --------
__device__ __align__(128) float  g_xt[B_*D_*L_];        // x transposed [b][d][l]
__device__ __align__(128) float2 g_Xf[B_*D_*N2];        // packed rfft of x rows
__device__ __align__(128) float2 g_Kf[C_*D_*N2];        // packed rfft of kernel rows
__device__ __align__(128) float2 g_tw[NFFT/2];          // e^{-2pi i k/8192}
// bf16 split conv output, [b][cd][l] (K-as-rows for trans-ldmatrix A)
__device__ __align__(128) __nv_bfloat16 g_yh[(size_t)B_*CD_*L_];
__device__ __align__(128) __nv_bfloat16 g_yl[(size_t)B_*CD_*L_];
// bf16 split operands for tensor-core GEMMs
__device__ __align__(128) __nv_bfloat16 g_wt_hi[D_*CD_];             // out_w^T [j][cd]
__device__ __align__(128) __nv_bfloat16 g_wt_lo[D_*CD_];
__device__ __align__(128) __nv_bfloat16 g_ut_hi[(size_t)B_*L_*D_];   // u split [b*L+l][d]
__device__ __align__(128) __nv_bfloat16 g_ut_lo[(size_t)B_*L_*D_];
__device__ __align__(128) __nv_bfloat16 g_w2_hi[D_*D_];              // in_w^T [n][k]
__device__ __align__(128) __nv_bfloat16 g_w2_lo[D_*D_];

// single dynamic smem symbol shared by all kernels
extern __shared__ char dynsmem[];

// -------- twiddle table --------
__global__ void k_tw() {
    int k = blockIdx.x*blockDim.x + threadIdx.x;
    if (k < NFFT/2) {
        double a = -2.0*M_PI*(double)k/(double)NFFT;
        g_tw[k] = make_float2((float)cos(a), (float)sin(a));
    }
}

// -------- split u into bf16 hi/lo (already K-major) --------
__global__ __launch_bounds__(256) void k_usplit(const float* __restrict__ u) {
    size_t e = ((size_t)blockIdx.x*blockDim.x + threadIdx.x)*2;
    float2 v = *(const float2*)&u[e];
    __nv_bfloat16 h0 = __float2bfloat16(v.x);
    __nv_bfloat16 h1 = __float2bfloat16(v.y);
    __nv_bfloat16 l0 = __float2bfloat16(v.x - __bfloat162float(h0));
    __nv_bfloat16 l1 = __float2bfloat16(v.y - __bfloat162float(h1));
    __nv_bfloat162 hh; hh.x = h0; hh.y = h1;
    __nv_bfloat162 ll; ll.x = l0; ll.y = l1;
    *(__nv_bfloat162*)&g_ut_hi[e] = hh;
    *(__nv_bfloat162*)&g_ut_lo[e] = ll;
}

// -------- transpose + split in_w [k][n] -> [n][k] --------
__global__ __launch_bounds__(256) void k_w2tr(const float* __restrict__ inw) {
    __shared__ float t[32][33];
    int k0 = blockIdx.x*32, j0 = blockIdx.y*32;
    int tx = threadIdx.x, ty = threadIdx.y;
#pragma unroll
    for (int r = 0; r < 32; r += 8)
        t[ty+r][tx] = inw[(size_t)(k0+ty+r)*D_ + j0+tx];
    __syncthreads();
#pragma unroll
    for (int r = 0; r < 32; r += 8) {
        float v = t[tx][ty+r];
        __nv_bfloat16 h = __float2bfloat16(v);
        __nv_bfloat16 lo = __float2bfloat16(v - __bfloat162float(h));
        size_t o = (size_t)(j0+ty+r)*D_ + k0+tx;
        g_w2_hi[o] = h; g_w2_lo[o] = lo;
    }
}

// -------- transpose + split out_w [cd][j] -> [j][cd] --------
__global__ __launch_bounds__(256) void k_wtr(const float* __restrict__ outw) {
    __shared__ float t[32][33];
    int k0 = blockIdx.x*32, j0 = blockIdx.y*32;
    int tx = threadIdx.x, ty = threadIdx.y;
#pragma unroll
    for (int r = 0; r < 32; r += 8)
        t[ty+r][tx] = outw[(size_t)(k0+ty+r)*D_ + j0+tx];
    __syncthreads();
#pragma unroll
    for (int r = 0; r < 32; r += 8) {
        float v = t[tx][ty+r];
        __nv_bfloat16 h = __float2bfloat16(v);
        __nv_bfloat16 lo = __float2bfloat16(v - __bfloat162float(h));
        size_t o = (size_t)(j0+ty+r)*CD_ + k0+tx;
        g_wt_hi[o] = h; g_wt_lo[o] = lo;
    }
}

// ======== radix-8-fused FFT on N2=4096 complex points in shared ========
// Input must ALREADY be at bit-reversed (SWZ'd) positions; output natural.
__device__ __forceinline__ void bf2(float2& a, float2& b, float2 w, bool inv) {
    float wy = inv ? -w.y : w.y;
    float brx = b.x*w.x - b.y*wy;
    float bry = b.x*wy + b.y*w.x;
    b.x = a.x - brx; b.y = a.y - bry;
    a.x += brx;      a.y += bry;
}

// requires blockDim.x == 512; caller must __syncthreads() before calling
__device__ __forceinline__ void block_fft(float2* s, int tid, bool inv) {
#pragma unroll
    for (int sp = 0; sp < LOG2N2; sp += 3) {
        int half = 1 << sp;
        int pos  = tid & (half - 1);
        int base = ((tid >> sp) << (sp + 3)) | pos;
        float2 v[8];
#pragma unroll
        for (int q = 0; q < 8; ++q) v[q] = s[SWZ(base + q*half)];
        int stepA = NFFT >> (sp + 1);
        int stepB = NFFT >> (sp + 2);
        int stepC = NFFT >> (sp + 3);
        float2 wA = __ldg(&g_tw[pos*stepA]);
        bf2(v[0], v[1], wA, inv); bf2(v[2], v[3], wA, inv);
        bf2(v[4], v[5], wA, inv); bf2(v[6], v[7], wA, inv);
        float2 wB0 = __ldg(&g_tw[pos*stepB]), wB1 = __ldg(&g_tw[(pos+half)*stepB]);
        bf2(v[0], v[2], wB0, inv); bf2(v[1], v[3], wB1, inv);
        bf2(v[4], v[6], wB0, inv); bf2(v[5], v[7], wB1, inv);
        float2 wC0 = __ldg(&g_tw[pos*stepC]),        wC1 = __ldg(&g_tw[(pos+half)*stepC]);
        float2 wC2 = __ldg(&g_tw[(pos+2*half)*stepC]), wC3 = __ldg(&g_tw[(pos+3*half)*stepC]);
        bf2(v[0], v[4], wC0, inv); bf2(v[1], v[5], wC1, inv);
        bf2(v[2], v[6], wC2, inv); bf2(v[3], v[7], wC3, inv);
#pragma unroll
        for (int q = 0; q < 8; ++q) s[SWZ(base + q*half)] = v[q];
        __syncthreads();
    }
}

#define SMEM_FFT (N2 * (int)sizeof(float2))   // 32 KB data only

__device__ __forceinline__ float2 ldcs2(const float2* p) {
    float2 r;
    asm volatile("ld.global.cs.v2.f32 {%0,%1}, [%2];" : "=f"(r.x), "=f"(r.y) : "l"(p));
    return r;
}

// -------- forward rfft of real rows (load straight into brev positions) ----
__global__ __launch_bounds__(512) void k_fft_fwd(const float* __restrict__ kern, int mode) {
    float2* s = (float2*)dynsmem;
    int tid = threadIdx.x, bs = blockDim.x;
    size_t row = blockIdx.x;
    const float* src = mode ? (kern + row*L_) : (g_xt + row*L_);
    for (int m = tid; m < N2; m += bs) {
        float2 v = (m < L_/2) ? ldcs2((const float2*)&src[2*m])
                              : make_float2(0.f, 0.f);
        s[SWZ(BREV(m))] = v;
    }
    __syncthreads();
    block_fft(s, tid, false);
    float2* dst = (mode ? g_Kf : g_Xf) + row*(size_t)N2;
    for (int k = tid; k < N2; k += bs) {
        if (k == 0) {
            float2 z0 = s[SWZ(0)];
            dst[0] = make_float2(z0.x + z0.y, z0.x - z0.y);
        } else {
            float2 A = s[SWZ(k)], Bm = s[SWZ(N2 - k)];
            float2 E = make_float2(0.5f*(A.x + Bm.x), 0.5f*(A.y - Bm.y));
            float2 O = make_float2(0.5f*(A.y + Bm.y), -0.5f*(A.x - Bm.x));
            float2 w = __ldg(&g_tw[k]);
            dst[k] = make_float2(E.x + w.x*O.x - w.y*O.y,
                                 E.y + w.x*O.y + w.y*O.x);
        }
    }
}

// ---- spectrum product (dmat folded: K' = K + dsc) fused with inverse
// Hermitian pack (brev scatter) + inverse FFT + bf16 split epilogue ----
__global__ __launch_bounds__(512) void k_conv_ifft(const float* __restrict__ dmat) {
    float2* s = (float2*)dynsmem;
    int tid = threadIdx.x, bs = blockDim.x;
    int idx = blockIdx.x;
    int bb = idx / CD_;
    int cd = idx - bb*CD_;
    int d  = cd & (D_-1);
    const float2* xf = g_Xf + ((size_t)(bb*D_ + d))*N2;
    const float2* kf = g_Kf + (size_t)cd*N2;
    float dsc = __ldg(&dmat[cd]);
    for (int k = tid; k < N2/2; k += bs) {
        if (k == 0) {
            float2 a0 = ldcs2(&xf[0]), b0 = ldcs2(&kf[0]);
            float y0 = a0.x*(b0.x + dsc), yn = a0.y*(b0.y + dsc);
            s[SWZ(0)] = make_float2(0.5f*(y0 + yn), 0.5f*(y0 - yn));   // BREV(0)=0
            float2 ah = ldcs2(&xf[N2/2]), bh = ldcs2(&kf[N2/2]);
            bh.x += dsc;
            float2 Yh = make_float2(ah.x*bh.x - ah.y*bh.y, ah.x*bh.y + ah.y*bh.x);
            s[SWZ(1)] = make_float2(Yh.x, -Yh.y);                       // BREV(N2/2)=1
        } else {
            float2 a  = ldcs2(&xf[k]),      b  = ldcs2(&kf[k]);
            float2 a2 = ldcs2(&xf[N2 - k]), b2 = ldcs2(&kf[N2 - k]);
            b.x += dsc; b2.x += dsc;
            float2 Yk = make_float2(a.x*b.x - a.y*b.y,   a.x*b.y + a.y*b.x);
            float2 Ym = make_float2(a2.x*b2.x - a2.y*b2.y, a2.x*b2.y + a2.y*b2.x);
            float2 E  = make_float2(0.5f*(Yk.x + Ym.x), 0.5f*(Yk.y - Ym.y));
            float2 Ow = make_float2(0.5f*(Yk.x - Ym.x), 0.5f*(Yk.y + Ym.y));
            float2 w = __ldg(&g_tw[k]);
            float2 O = make_float2(Ow.x*w.x + Ow.y*w.y, Ow.y*w.x - Ow.x*w.y);
            s[SWZ(BREV(k))]      = make_float2(E.x - O.y,  E.y + O.x);
            s[SWZ(BREV(N2 - k))] = make_float2(E.x + O.y, -E.y + O.x);
        }
    }
    __syncthreads();
    block_fft(s, tid, true);
    __nv_bfloat162* yh = (__nv_bfloat162*)(g_yh + (size_t)idx*L_);
    __nv_bfloat162* yl = (__nv_bfloat162*)(g_yl + (size_t)idx*L_);
    const float invn = 1.0f/(float)N2;
    for (int m = tid; m < L_/2; m += bs) {
        float2 z = s[SWZ(m)];
        float ox = z.x*invn;
        float oy = z.y*invn;
        __nv_bfloat16 h0 = __float2bfloat16(ox);
        __nv_bfloat16 h1 = __float2bfloat16(oy);
        __nv_bfloat16 l0 = __float2bfloat16(ox - __bfloat162float(h0));
        __nv_bfloat16 l1 = __float2bfloat16(oy - __bfloat162float(h1));
        __nv_bfloat162 hh; hh.x = h0; hh.y = h1;
        __nv_bfloat162 ll; ll.x = l0; ll.y = l1;
        yh[m] = hh;
        yl[m] = ll;
    }
}

// ======== mma.sync bf16 split GEMM machinery ========
#define KP 40   // smem row pitch (bf16): 32 data + 8 pad
#define BUFE (128*KP)            // elements per buffer
#define BUFB (BUFE*2)            // bytes per buffer
#define SM_MMA (2*4*BUFB)        // 2 stages x 4 buffers = 81920 B

__device__ __forceinline__ uint32_t smem_u32(const void* p) {
    uint32_t a;
    asm("{ .reg .u64 t; cvta.to.shared.u64 t, %1; cvt.u32.u64 %0, t; }" : "=r"(a) : "l"(p));
    return a;
}
__device__ __forceinline__ void cpa16(uint32_t saddr, const void* g) {
    asm volatile("cp.async.cg.shared.global [%0], [%1], 16;" :: "r"(saddr), "l"(g));
}
__device__ __forceinline__ void ldsm4(uint32_t& r0, uint32_t& r1, uint32_t& r2,
                                      uint32_t& r3, uint32_t addr) {
    asm volatile("ldmatrix.sync.aligned.m8n8.x4.shared.b16 {%0,%1,%2,%3}, [%4];"
                 : "=r"(r0), "=r"(r1), "=r"(r2), "=r"(r3) : "r"(addr));
}
__device__ __forceinline__ void ldsm4t(uint32_t& r0, uint32_t& r1, uint32_t& r2,
                                       uint32_t& r3, uint32_t addr) {
    asm volatile("ldmatrix.sync.aligned.m8n8.x4.trans.shared.b16 {%0,%1,%2,%3}, [%4];"
                 : "=r"(r0), "=r"(r1), "=r"(r2), "=r"(r3) : "r"(addr));
}
__device__ __forceinline__ void ldsm2(uint32_t& r0, uint32_t& r1, uint32_t addr) {
    asm volatile("ldmatrix.sync.aligned.m8n8.x2.shared.b16 {%0,%1}, [%2];"
                 : "=r"(r0), "=r"(r1) : "r"(addr));
}
__device__ __forceinline__ void mma16816(float* d, const uint32_t* a, const uint32_t* b) {
    asm volatile(
        "mma.sync.aligned.m16n8k16.row.col.f32.bf16.bf16.f32 "
        "{%0,%1,%2,%3}, {%4,%5,%6,%7}, {%8,%9}, {%0,%1,%2,%3};"
        : "+f"(d[0]), "+f"(d[1]), "+f"(d[2]), "+f"(d[3])
        : "r"(a[0]), "r"(a[1]), "r"(a[2]), "r"(a[3]), "r"(b[0]), "r"(b[1]));
}

// ======== k_mma_in: in_proj GEMM (A row-major [m][k]) ======
__global__ __launch_bounds__(256) void k_mma_in(const float* __restrict__ bias) {
    const int KDIM = D_;
    uint32_t sbase = smem_u32(dynsmem);
    int tid = threadIdx.x, wid = tid >> 5, lid = tid & 31;
    int n0 = blockIdx.x*128, m0 = blockIdx.y*128;
    int wm = wid & 3, wn = wid >> 2;

    float acc[2][8][4];
#pragma unroll
    for (int i = 0; i < 2; ++i)
#pragma unroll
        for (int j = 0; j < 8; ++j)
#pragma unroll
            for (int c = 0; c < 4; ++c) acc[i][j][c] = 0.f;

    int r0i = tid >> 2, c0i = tid & 3;
    int r1i = r0i + 64;
    const __nv_bfloat16* pA0h = g_ut_hi + (size_t)(m0 + r0i)*KDIM + c0i*8;
    const __nv_bfloat16* pA1h = g_ut_hi + (size_t)(m0 + r1i)*KDIM + c0i*8;
    const __nv_bfloat16* pA0l = g_ut_lo + (size_t)(m0 + r0i)*KDIM + c0i*8;
    const __nv_bfloat16* pA1l = g_ut_lo + (size_t)(m0 + r1i)*KDIM + c0i*8;
    const __nv_bfloat16* pB0h = g_w2_hi + (size_t)(n0 + r0i)*KDIM + c0i*8;
    const __nv_bfloat16* pB1h = g_w2_hi + (size_t)(n0 + r1i)*KDIM + c0i*8;
    const __nv_bfloat16* pB0l = g_w2_lo + (size_t)(n0 + r0i)*KDIM + c0i*8;
    const __nv_bfloat16* pB1l = g_w2_lo + (size_t)(n0 + r1i)*KDIM + c0i*8;
    uint32_t so0 = (r0i*KP + c0i*8)*2;
    uint32_t so1 = (r1i*KP + c0i*8)*2;

    const int NS = KDIM/32;

#define ISSUE_IN(s, stg) do {                                                 \
        int _k0 = (s)*32;                                                     \
        uint32_t _st = sbase + (stg)*4*BUFB;                                  \
        cpa16(_st + 0*BUFB + so0, pA0h + _k0);                                \
        cpa16(_st + 0*BUFB + so1, pA1h + _k0);                                \
        cpa16(_st + 1*BUFB + so0, pA0l + _k0);                                \
        cpa16(_st + 1*BUFB + so1, pA1l + _k0);                                \
        cpa16(_st + 2*BUFB + so0, pB0h + _k0);                                \
        cpa16(_st + 2*BUFB + so1, pB1h + _k0);                                \
        cpa16(_st + 3*BUFB + so0, pB0l + _k0);                                \
        cpa16(_st + 3*BUFB + so1, pB1l + _k0);                                \
        asm volatile("cp.async.commit_group;");                               \
    } while (0)

    ISSUE_IN(0, 0);

    for (int s = 0; s < NS; ++s) {
        if (s + 1 < NS) {
            ISSUE_IN(s + 1, (s + 1) & 1);
            asm volatile("cp.async.wait_group 1;");
        } else {
            asm volatile("cp.async.wait_group 0;");
        }
        __syncthreads();
        uint32_t soff = (uint32_t)(s & 1)*4*BUFB;
        uint32_t aAh = sbase + soff + 0*BUFB;
        uint32_t aAl = sbase + soff + 1*BUFB;
        uint32_t aBh = sbase + soff + 2*BUFB;
        uint32_t aBl = sbase + soff + 3*BUFB;
#pragma unroll
        for (int h = 0; h < 2; ++h) {
            int koff = h*16;
            uint32_t ah[2][4], al[2][4];
            {
                int mat = lid >> 3, rin = lid & 7;
                int arow = wm*32 + ((mat & 1) ? 8 : 0) + rin;
                int acol = koff + ((mat >> 1) ? 8 : 0);
#pragma unroll
                for (int mt = 0; mt < 2; ++mt) {
                    uint32_t off = ((arow + mt*16)*KP + acol)*2;
                    ldsm4(ah[mt][0], ah[mt][1], ah[mt][2], ah[mt][3], aAh + off);
                    ldsm4(al[mt][0], al[mt][1], al[mt][2], al[mt][3], aAl + off);
                }
            }
            {
                int mat = (lid >> 3) & 1, rin = lid & 7;
                int brow_base = wn*64 + rin;
                int bcol = koff + mat*8;
#pragma unroll
                for (int jt = 0; jt < 8; ++jt) {
                    uint32_t off = ((brow_base + jt*8)*KP + bcol)*2;
                    uint32_t bh[2], bl[2];
                    ldsm2(bh[0], bh[1], aBh + off);
                    ldsm2(bl[0], bl[1], aBl + off);
#pragma unroll
                    for (int mt = 0; mt < 2; ++mt) {
                        mma16816(acc[mt][jt], ah[mt], bh);
                        mma16816(acc[mt][jt], ah[mt], bl);
                        mma16816(acc[mt][jt], al[mt], bh);
                    }
                }
            }
        }
        __syncthreads();
    }
#undef ISSUE_IN

    int qr = lid >> 2, qc = lid & 3;
#pragma unroll
    for (int mt = 0; mt < 2; ++mt) {
#pragma unroll
        for (int jt = 0; jt < 8; ++jt) {
            int n = n0 + wn*64 + jt*8 + qc*2;
            int m_a = m0 + wm*32 + mt*16 + qr;
            int m_b = m_a + 8;
            float b0 = bias[n], b1 = bias[n+1];
            int ba = m_a >> 12, la = m_a & (L_-1);
            int bbv = m_b >> 12, lb = m_b & (L_-1);
            g_xt[((size_t)(ba*D_  + n  ))*L_ + la] = acc[mt][jt][0] + b0;
            g_xt[((size_t)(ba*D_  + n+1))*L_ + la] = acc[mt][jt][1] + b1;
            g_xt[((size_t)(bbv*D_ + n  ))*L_ + lb] = acc[mt][jt][2] + b0;
            g_xt[((size_t)(bbv*D_ + n+1))*L_ + lb] = acc[mt][jt][3] + b1;
        }
    }
}

// ======== k_mma_out: out_proj GEMM, A from [k][m] via ldmatrix.trans ========
#define KPA  136                 // A smem pitch (bf16): 128 data + 8 pad
#define ABUF (32*KPA*2)          // 8704 B per A buffer (32 k-rows x 128 m)
#define BBUF (128*KP*2)          // 10240 B per B buffer
#define STGB (2*ABUF + 2*BBUF)   // bytes per stage
#define SM_MO (2*STGB)           // 75776 B

__global__ __launch_bounds__(256) void k_mma_out(const float* __restrict__ outb,
                                                 float* __restrict__ out) {
    const int KDIM = CD_;
    uint32_t sbase = smem_u32(dynsmem);
    int tid = threadIdx.x, wid = tid >> 5, lid = tid & 31;
    int n0 = blockIdx.x*128, m0 = blockIdx.y*128;
    int wm = wid & 3, wn = wid >> 2;
    int bbm = m0 >> 12;                 // batch of this m-tile
    int l0  = m0 & (L_-1);

    float acc[2][8][4];
#pragma unroll
    for (int i = 0; i < 2; ++i)
#pragma unroll
        for (int j = 0; j < 8; ++j)
#pragma unroll
            for (int c = 0; c < 4; ++c) acc[i][j][c] = 0.f;

    // A: [k][m] rows; thread handles rows rA and rA+16, chunk cA
    int rA = tid >> 4, cA = tid & 15;
    const __nv_bfloat16* Ahb = g_yh + (size_t)bbm*CD_*L_ + l0;
    const __nv_bfloat16* Alb = g_yl + (size_t)bbm*CD_*L_ + l0;
    uint32_t soA0 = (rA*KPA + cA*8)*2;
    uint32_t soA1 = ((rA+16)*KPA + cA*8)*2;
    // B: [n][k] rows
    int r0i = tid >> 2, c0i = tid & 3;
    int r1i = r0i + 64;
    const __nv_bfloat16* pB0h = g_wt_hi + (size_t)(n0 + r0i)*KDIM + c0i*8;
    const __nv_bfloat16* pB1h = g_wt_hi + (size_t)(n0 + r1i)*KDIM + c0i*8;
    const __nv_bfloat16* pB0l = g_wt_lo + (size_t)(n0 + r0i)*KDIM + c0i*8;
    const __nv_bfloat16* pB1l = g_wt_lo + (size_t)(n0 + r1i)*KDIM + c0i*8;
    uint32_t soB0 = (r0i*KP + c0i*8)*2;
    uint32_t soB1 = (r1i*KP + c0i*8)*2;

    const int NS = KDIM/32;

#define ISSUE_OUT(s, stg) do {                                                \
        int _k0 = (s)*32;                                                     \
        uint32_t _st = sbase + (stg)*STGB;                                    \
        cpa16(_st + soA0,            Ahb + (size_t)(_k0 + rA)*L_ + cA*8);     \
        cpa16(_st + soA1,            Ahb + (size_t)(_k0 + rA + 16)*L_ + cA*8);\
        cpa16(_st + ABUF + soA0,     Alb + (size_t)(_k0 + rA)*L_ + cA*8);     \
        cpa16(_st + ABUF + soA1,     Alb + (size_t)(_k0 + rA + 16)*L_ + cA*8);\
        cpa16(_st + 2*ABUF + soB0,        pB0h + _k0);                        \
        cpa16(_st + 2*ABUF + soB1,        pB1h + _k0);                        \
        cpa16(_st + 2*ABUF + BBUF + soB0, pB0l + _k0);                        \
        cpa16(_st + 2*ABUF + BBUF + soB1, pB1l + _k0);                        \
        asm volatile("cp.async.commit_group;");                               \
    } while (0)

    ISSUE_OUT(0, 0);

    for (int s = 0; s < NS; ++s) {
        if (s + 1 < NS) {
            ISSUE_OUT(s + 1, (s + 1) & 1);
            asm volatile("cp.async.wait_group 1;");
        } else {
            asm volatile("cp.async.wait_group 0;");
        }
        __syncthreads();
        uint32_t soff = (uint32_t)(s & 1)*STGB;
        uint32_t aAh = sbase + soff;
        uint32_t aAl = sbase + soff + ABUF;
        uint32_t aBh = sbase + soff + 2*ABUF;
        uint32_t aBl = sbase + soff + 2*ABUF + BBUF;
#pragma unroll
        for (int h = 0; h < 2; ++h) {
            int koff = h*16;
            uint32_t ah[2][4], al[2][4];
            {
                int mat = lid >> 3, rin = lid & 7;
                int akrow = koff + ((mat >> 1) ? 8 : 0) + rin;
                int amcol = wm*32 + ((mat & 1) ? 8 : 0);
#pragma unroll
                for (int mt = 0; mt < 2; ++mt) {
                    uint32_t off = (akrow*KPA + amcol + mt*16)*2;
                    ldsm4t(ah[mt][0], ah[mt][1], ah[mt][2], ah[mt][3], aAh + off);
                    ldsm4t(al[mt][0], al[mt][1], al[mt][2], al[mt][3], aAl + off);
                }
            }
            {
                int mat = (lid >> 3) & 1, rin = lid & 7;
                int brow_base = wn*64 + rin;
                int bcol = koff + mat*8;
#pragma unroll
                for (int jt = 0; jt < 8; ++jt) {
                    uint32_t off = ((brow_base + jt*8)*KP + bcol)*2;
                    uint32_t bh[2], bl[2];
                    ldsm2(bh[0], bh[1], aBh + off);
                    ldsm2(bl[0], bl[1], aBl + off);
#pragma unroll
                    for (int mt = 0; mt < 2; ++mt) {
                        mma16816(acc[mt][jt], ah[mt], bh);
                        mma16816(acc[mt][jt], ah[mt], bl);
                        mma16816(acc[mt][jt], al[mt], bh);
                    }
                }
            }
        }
        __syncthreads();
    }
#undef ISSUE_OUT

    int qr = lid >> 2, qc = lid & 3;
#pragma unroll
    for (int mt = 0; mt < 2; ++mt) {
#pragma unroll
        for (int jt = 0; jt < 8; ++jt) {
            int n = n0 + wn*64 + jt*8 + qc*2;
            int m_a = m0 + wm*32 + mt*16 + qr;
            int m_b = m_a + 8;
            float b0 = outb[n], b1 = outb[n+1];
            int ba = m_a >> 12, la = m_a & (L_-1);
            int bbv = m_b >> 12, lb = m_b & (L_-1);
            float2 va = make_float2(acc[mt][jt][0] + b0, acc[mt][jt][1] + b1);
            float2 vb = make_float2(acc[mt][jt][2] + b0, acc[mt][jt][3] + b1);
            *(float2*)&out[((size_t)(ba*L_ + la))*D_ + n] = va;
            *(float2*)&out[((size_t)(bbv*L_ + lb))*D_ + n] = vb;
        }
    }
}

extern "C" void kernel_launch(void* const* d_in, const int* in_sizes, int n_in,
                              void* d_out, int out_size) {
    const float* u    = (const float*)d_in[0];
    const float* in_w = (const float*)d_in[1];
    const float* in_b = (const float*)d_in[2];
    const float* kern = (const float*)d_in[3];
    const float* dmat = (const float*)d_in[4];
    const float* outw = (const float*)d_in[5];
    const float* outb = (const float*)d_in[6];
    float* out = (float*)d_out;

    cudaFuncSetAttribute(k_fft_fwd,   cudaFuncAttributeMaxDynamicSharedMemorySize, SMEM_FFT);
    cudaFuncSetAttribute(k_conv_ifft, cudaFuncAttributeMaxDynamicSharedMemorySize, SMEM_FFT);
    cudaFuncSetAttribute(k_mma_out,   cudaFuncAttributeMaxDynamicSharedMemorySize, SM_MO);
    cudaFuncSetAttribute(k_mma_in,    cudaFuncAttributeMaxDynamicSharedMemorySize, SM_MMA);

    k_tw<<<(NFFT/2 + 255)/256, 256>>>();

    k_usplit<<<(B_*L_*D_/2)/256, 256>>>(u);
    { dim3 g(D_/32, D_/32);  k_w2tr<<<g, dim3(32,8)>>>(in_w); }
    { dim3 g(CD_/32, D_/32); k_wtr<<<g, dim3(32,8)>>>(outw); }

    { dim3 g(D_/128, (B_*L_)/128); k_mma_in<<<g, 256, SM_MMA>>>(in_b); }

    k_fft_fwd<<<B_*D_, 512, SMEM_FFT>>>(kern, 0);   // x rows
    k_fft_fwd<<<C_*D_, 512, SMEM_FFT>>>(kern, 1);   // kernel rows

    k_conv_ifft<<<B_*C_*D_, 512, SMEM_FFT>>>(dmat);

    { dim3 g(D_/128, (B_*L_)/128); k_mma_out<<<g, 256, SM_MO>>>(outb, out); }
}

// round 15
// speedup vs baseline: 1.0845x; 1.0024x over previous
#include <cuda_runtime.h>
#include <cuda_bf16.h>
#include <cstdint>
#include <math.h>

#define B_    2
#define L_    4096
#define D_    1024
#define C_    4
#define NFFT  8192          // conv length
#define N2    4096          // complex FFT length (real-packed)
#define LOG2N2 12
#define CD_   (C_*D_)

// XOR swizzle (bijective on [0,4096)); conflict-free for butterflies AND
// for the bit-reversed scatter writes.
#define SWZ(i) ((i) ^ (((i) >> 4) & 15) ^ (((i) >> 8) & 15))
#define BREV(i) ((int)(__brev((unsigned)(i)) >> 20))

// -------- scratch (device globals: allocation-free) --------
__device__ __align__(128) float  g_xt[B_*D_*L_];        // x transposed [b][d][l]
__device__ __align__(128) float2 g_Xf[B_*D_*N2];        // packed rfft of x rows
__device__ __align__(128) float2 g_Kf[C_*D_*N2];        // packed rfft of kernel rows
__device__ __align__(128) float2 g_tw[NFFT/2];          // e^{-2pi i k/8192}
// bf16 split conv output, [b][cd][l] (K-as-rows for trans-ldmatrix A)
__device__ __align__(128) __nv_bfloat16 g_yh[(size_t)B_*CD_*L_];
__device__ __align__(128) __nv_bfloat16 g_yl[(size_t)B_*CD_*L_];
// bf16 split operands for tensor-core GEMMs
__device__ __align__(128) __nv_bfloat16 g_wt_hi[D_*CD_];             // out_w^T [j][cd]
__device__ __align__(128) __nv_bfloat16 g_wt_lo[D_*CD_];
__device__ __align__(128) __nv_bfloat16 g_ut_hi[(size_t)B_*L_*D_];   // u split [b*L+l][d]
__device__ __align__(128) __nv_bfloat16 g_ut_lo[(size_t)B_*L_*D_];
__device__ __align__(128) __nv_bfloat16 g_w2_hi[D_*D_];              // in_w^T [n][k]
__device__ __align__(128) __nv_bfloat16 g_w2_lo[D_*D_];

// single dynamic smem symbol shared by all kernels
extern __shared__ char dynsmem[];

// -------- twiddle table --------
__global__ void k_tw() {
    int k = blockIdx.x*blockDim.x + threadIdx.x;
    if (k < NFFT/2) {
        double a = -2.0*M_PI*(double)k/(double)NFFT;
        g_tw[k] = make_float2((float)cos(a), (float)sin(a));
    }
}

// -------- split u into bf16 hi/lo (already K-major) --------
__global__ __launch_bounds__(256) void k_usplit(const float* __restrict__ u) {
    size_t e = ((size_t)blockIdx.x*blockDim.x + threadIdx.x)*2;
    float2 v = *(const float2*)&u[e];
    __nv_bfloat16 h0 = __float2bfloat16(v.x);
    __nv_bfloat16 h1 = __float2bfloat16(v.y);
    __nv_bfloat16 l0 = __float2bfloat16(v.x - __bfloat162float(h0));
    __nv_bfloat16 l1 = __float2bfloat16(v.y - __bfloat162float(h1));
    __nv_bfloat162 hh; hh.x = h0; hh.y = h1;
    __nv_bfloat162 ll; ll.x = l0; ll.y = l1;
    *(__nv_bfloat162*)&g_ut_hi[e] = hh;
    *(__nv_bfloat162*)&g_ut_lo[e] = ll;
}

// -------- transpose + split in_w [k][n] -> [n][k] --------
__global__ __launch_bounds__(256) void k_w2tr(const float* __restrict__ inw) {
    __shared__ float t[32][33];
    int k0 = blockIdx.x*32, j0 = blockIdx.y*32;
    int tx = threadIdx.x, ty = threadIdx.y;
#pragma unroll
    for (int r = 0; r < 32; r += 8)
        t[ty+r][tx] = inw[(size_t)(k0+ty+r)*D_ + j0+tx];
    __syncthreads();
#pragma unroll
    for (int r = 0; r < 32; r += 8) {
        float v = t[tx][ty+r];
        __nv_bfloat16 h = __float2bfloat16(v);
        __nv_bfloat16 lo = __float2bfloat16(v - __bfloat162float(h));
        size_t o = (size_t)(j0+ty+r)*D_ + k0+tx;
        g_w2_hi[o] = h; g_w2_lo[o] = lo;
    }
}

// -------- transpose + split out_w [cd][j] -> [j][cd] --------
__global__ __launch_bounds__(256) void k_wtr(const float* __restrict__ outw) {
    __shared__ float t[32][33];
    int k0 = blockIdx.x*32, j0 = blockIdx.y*32;
    int tx = threadIdx.x, ty = threadIdx.y;
#pragma unroll
    for (int r = 0; r < 32; r += 8)
        t[ty+r][tx] = outw[(size_t)(k0+ty+r)*D_ + j0+tx];
    __syncthreads();
#pragma unroll
    for (int r = 0; r < 32; r += 8) {
        float v = t[tx][ty+r];
        __nv_bfloat16 h = __float2bfloat16(v);
        __nv_bfloat16 lo = __float2bfloat16(v - __bfloat162float(h));
        size_t o = (size_t)(j0+ty+r)*CD_ + k0+tx;
        g_wt_hi[o] = h; g_wt_lo[o] = lo;
    }
}

// ======== radix-8-fused FFT on N2=4096 complex points in shared ========
// Input must ALREADY be at bit-reversed (SWZ'd) positions; output natural.
__device__ __forceinline__ void bf2(float2& a, float2& b, float2 w, bool inv) {
    float wy = inv ? -w.y : w.y;
    float brx = b.x*w.x - b.y*wy;
    float bry = b.x*wy + b.y*w.x;
    b.x = a.x - brx; b.y = a.y - bry;
    a.x += brx;      a.y += bry;
}

// requires blockDim.x == 512; caller must __syncthreads() before calling
__device__ __forceinline__ void block_fft(float2* s, int tid, bool inv) {
#pragma unroll
    for (int sp = 0; sp < LOG2N2; sp += 3) {
        int half = 1 << sp;
        int pos  = tid & (half - 1);
        int base = ((tid >> sp) << (sp + 3)) | pos;
        float2 v[8];
#pragma unroll
        for (int q = 0; q < 8; ++q) v[q] = s[SWZ(base + q*half)];
        int stepA = NFFT >> (sp + 1);
        int stepB = NFFT >> (sp + 2);
        int stepC = NFFT >> (sp + 3);
        float2 wA = __ldg(&g_tw[pos*stepA]);
        bf2(v[0], v[1], wA, inv); bf2(v[2], v[3], wA, inv);
        bf2(v[4], v[5], wA, inv); bf2(v[6], v[7], wA, inv);
        float2 wB0 = __ldg(&g_tw[pos*stepB]), wB1 = __ldg(&g_tw[(pos+half)*stepB]);
        bf2(v[0], v[2], wB0, inv); bf2(v[1], v[3], wB1, inv);
        bf2(v[4], v[6], wB0, inv); bf2(v[5], v[7], wB1, inv);
        float2 wC0 = __ldg(&g_tw[pos*stepC]),        wC1 = __ldg(&g_tw[(pos+half)*stepC]);
        float2 wC2 = __ldg(&g_tw[(pos+2*half)*stepC]), wC3 = __ldg(&g_tw[(pos+3*half)*stepC]);
        bf2(v[0], v[4], wC0, inv); bf2(v[1], v[5], wC1, inv);
        bf2(v[2], v[6], wC2, inv); bf2(v[3], v[7], wC3, inv);
#pragma unroll
        for (int q = 0; q < 8; ++q) s[SWZ(base + q*half)] = v[q];
        __syncthreads();
    }
}

#define SMEM_FFT (N2 * (int)sizeof(float2))   // 32 KB data only

__device__ __forceinline__ float2 ldcs2(const float2* p) {
    float2 r;
    asm volatile("ld.global.cs.v2.f32 {%0,%1}, [%2];" : "=f"(r.x), "=f"(r.y) : "l"(p));
    return r;
}

// -------- forward rfft of real rows (load straight into brev positions) ----
__global__ __launch_bounds__(512) void k_fft_fwd(const float* __restrict__ kern, int mode) {
    float2* s = (float2*)dynsmem;
    int tid = threadIdx.x, bs = blockDim.x;
    size_t row = blockIdx.x;
    const float* src = mode ? (kern + row*L_) : (g_xt + row*L_);
    for (int m = tid; m < N2; m += bs) {
        float2 v = (m < L_/2) ? ldcs2((const float2*)&src[2*m])
                              : make_float2(0.f, 0.f);
        s[SWZ(BREV(m))] = v;
    }
    __syncthreads();
    block_fft(s, tid, false);
    float2* dst = (mode ? g_Kf : g_Xf) + row*(size_t)N2;
    for (int k = tid; k < N2; k += bs) {
        if (k == 0) {
            float2 z0 = s[SWZ(0)];
            dst[0] = make_float2(z0.x + z0.y, z0.x - z0.y);
        } else {
            float2 A = s[SWZ(k)], Bm = s[SWZ(N2 - k)];
            float2 E = make_float2(0.5f*(A.x + Bm.x), 0.5f*(A.y - Bm.y));
            float2 O = make_float2(0.5f*(A.y + Bm.y), -0.5f*(A.x - Bm.x));
            float2 w = __ldg(&g_tw[k]);
            dst[k] = make_float2(E.x + w.x*O.x - w.y*O.y,
                                 E.y + w.x*O.y + w.y*O.x);
        }
    }
}

// ---- spectrum product (dmat folded: K' = K + dsc) fused with inverse
// Hermitian pack (brev scatter) + inverse FFT + bf16 split epilogue ----
// block decode: cd = idx>>1, bb = idx&1 — adjacent block pairs share the
// same kf row (L2 reuse halves kf traffic); writes remain 2 ordered streams.
__global__ __launch_bounds__(512) void k_conv_ifft(const float* __restrict__ dmat) {
    float2* s = (float2*)dynsmem;
    int tid = threadIdx.x, bs = blockDim.x;
    int idx = blockIdx.x;
    int cd = idx >> 1;
    int bb = idx & 1;
    int d  = cd & (D_-1);
    const float2* xf = g_Xf + ((size_t)(bb*D_ + d))*N2;
    const float2* kf = g_Kf + (size_t)cd*N2;
    float dsc = __ldg(&dmat[cd]);
    for (int k = tid; k < N2/2; k += bs) {
        if (k == 0) {
            float2 a0 = ldcs2(&xf[0]), b0 = __ldg(&kf[0]);
            float y0 = a0.x*(b0.x + dsc), yn = a0.y*(b0.y + dsc);
            s[SWZ(0)] = make_float2(0.5f*(y0 + yn), 0.5f*(y0 - yn));   // BREV(0)=0
            float2 ah = ldcs2(&xf[N2/2]), bh = __ldg(&kf[N2/2]);
            bh.x += dsc;
            float2 Yh = make_float2(ah.x*bh.x - ah.y*bh.y, ah.x*bh.y + ah.y*bh.x);
            s[SWZ(1)] = make_float2(Yh.x, -Yh.y);                       // BREV(N2/2)=1
        } else {
            float2 a  = ldcs2(&xf[k]),      b  = __ldg(&kf[k]);
            float2 a2 = ldcs2(&xf[N2 - k]), b2 = __ldg(&kf[N2 - k]);
            b.x += dsc; b2.x += dsc;
            float2 Yk = make_float2(a.x*b.x - a.y*b.y,   a.x*b.y + a.y*b.x);
            float2 Ym = make_float2(a2.x*b2.x - a2.y*b2.y, a2.x*b2.y + a2.y*b2.x);
            float2 E  = make_float2(0.5f*(Yk.x + Ym.x), 0.5f*(Yk.y - Ym.y));
            float2 Ow = make_float2(0.5f*(Yk.x - Ym.x), 0.5f*(Yk.y + Ym.y));
            float2 w = __ldg(&g_tw[k]);
            float2 O = make_float2(Ow.x*w.x + Ow.y*w.y, Ow.y*w.x - Ow.x*w.y);
            s[SWZ(BREV(k))]      = make_float2(E.x - O.y,  E.y + O.x);
            s[SWZ(BREV(N2 - k))] = make_float2(E.x + O.y, -E.y + O.x);
        }
    }
    __syncthreads();
    block_fft(s, tid, true);
    size_t orow = (size_t)(bb*CD_ + cd)*L_;
    __nv_bfloat162* yh = (__nv_bfloat162*)(g_yh + orow);
    __nv_bfloat162* yl = (__nv_bfloat162*)(g_yl + orow);
    const float invn = 1.0f/(float)N2;
    for (int m = tid; m < L_/2; m += bs) {
        float2 z = s[SWZ(m)];
        float ox = z.x*invn;
        float oy = z.y*invn;
        __nv_bfloat16 h0 = __float2bfloat16(ox);
        __nv_bfloat16 h1 = __float2bfloat16(oy);
        __nv_bfloat16 l0 = __float2bfloat16(ox - __bfloat162float(h0));
        __nv_bfloat16 l1 = __float2bfloat16(oy - __bfloat162float(h1));
        __nv_bfloat162 hh; hh.x = h0; hh.y = h1;
        __nv_bfloat162 ll; ll.x = l0; ll.y = l1;
        yh[m] = hh;
        yl[m] = ll;
    }
}

// ======== mma.sync bf16 split GEMM machinery ========
#define KP 40   // smem row pitch (bf16): 32 data + 8 pad
#define BUFE (128*KP)            // elements per buffer
#define BUFB (BUFE*2)            // bytes per buffer
#define SM_MMA (2*4*BUFB)        // 2 stages x 4 buffers = 81920 B

__device__ __forceinline__ uint32_t smem_u32(const void* p) {
    uint32_t a;
    asm("{ .reg .u64 t; cvta.to.shared.u64 t, %1; cvt.u32.u64 %0, t; }" : "=r"(a) : "l"(p));
    return a;
}
__device__ __forceinline__ void cpa16(uint32_t saddr, const void* g) {
    asm volatile("cp.async.cg.shared.global [%0], [%1], 16;" :: "r"(saddr), "l"(g));
}
__device__ __forceinline__ void ldsm4(uint32_t& r0, uint32_t& r1, uint32_t& r2,
                                      uint32_t& r3, uint32_t addr) {
    asm volatile("ldmatrix.sync.aligned.m8n8.x4.shared.b16 {%0,%1,%2,%3}, [%4];"
                 : "=r"(r0), "=r"(r1), "=r"(r2), "=r"(r3) : "r"(addr));
}
__device__ __forceinline__ void ldsm4t(uint32_t& r0, uint32_t& r1, uint32_t& r2,
                                       uint32_t& r3, uint32_t addr) {
    asm volatile("ldmatrix.sync.aligned.m8n8.x4.trans.shared.b16 {%0,%1,%2,%3}, [%4];"
                 : "=r"(r0), "=r"(r1), "=r"(r2), "=r"(r3) : "r"(addr));
}
__device__ __forceinline__ void ldsm2(uint32_t& r0, uint32_t& r1, uint32_t addr) {
    asm volatile("ldmatrix.sync.aligned.m8n8.x2.shared.b16 {%0,%1}, [%2];"
                 : "=r"(r0), "=r"(r1) : "r"(addr));
}
__device__ __forceinline__ void mma16816(float* d, const uint32_t* a, const uint32_t* b) {
    asm volatile(
        "mma.sync.aligned.m16n8k16.row.col.f32.bf16.bf16.f32 "
        "{%0,%1,%2,%3}, {%4,%5,%6,%7}, {%8,%9}, {%0,%1,%2,%3};"
        : "+f"(d[0]), "+f"(d[1]), "+f"(d[2]), "+f"(d[3])
        : "r"(a[0]), "r"(a[1]), "r"(a[2]), "r"(a[3]), "r"(b[0]), "r"(b[1]));
}

// ======== k_mma_in: in_proj GEMM (A row-major [m][k]) ======
__global__ __launch_bounds__(256) void k_mma_in(const float* __restrict__ bias) {
    const int KDIM = D_;
    uint32_t sbase = smem_u32(dynsmem);
    int tid = threadIdx.x, wid = tid >> 5, lid = tid & 31;
    int n0 = blockIdx.x*128, m0 = blockIdx.y*128;
    int wm = wid & 3, wn = wid >> 2;

    float acc[2][8][4];
#pragma unroll
    for (int i = 0; i < 2; ++i)
#pragma unroll
        for (int j = 0; j < 8; ++j)
#pragma unroll
            for (int c = 0; c < 4; ++c) acc[i][j][c] = 0.f;

    int r0i = tid >> 2, c0i = tid & 3;
    int r1i = r0i + 64;
    const __nv_bfloat16* pA0h = g_ut_hi + (size_t)(m0 + r0i)*KDIM + c0i*8;
    const __nv_bfloat16* pA1h = g_ut_hi + (size_t)(m0 + r1i)*KDIM + c0i*8;
    const __nv_bfloat16* pA0l = g_ut_lo + (size_t)(m0 + r0i)*KDIM + c0i*8;
    const __nv_bfloat16* pA1l = g_ut_lo + (size_t)(m0 + r1i)*KDIM + c0i*8;
    const __nv_bfloat16* pB0h = g_w2_hi + (size_t)(n0 + r0i)*KDIM + c0i*8;
    const __nv_bfloat16* pB1h = g_w2_hi + (size_t)(n0 + r1i)*KDIM + c0i*8;
    const __nv_bfloat16* pB0l = g_w2_lo + (size_t)(n0 + r0i)*KDIM + c0i*8;
    const __nv_bfloat16* pB1l = g_w2_lo + (size_t)(n0 + r1i)*KDIM + c0i*8;
    uint32_t so0 = (r0i*KP + c0i*8)*2;
    uint32_t so1 = (r1i*KP + c0i*8)*2;

    const int NS = KDIM/32;

#define ISSUE_IN(s, stg) do {                                                 \
        int _k0 = (s)*32;                                                     \
        uint32_t _st = sbase + (stg)*4*BUFB;                                  \
        cpa16(_st + 0*BUFB + so0, pA0h + _k0);                                \
        cpa16(_st + 0*BUFB + so1, pA1h + _k0);                                \
        cpa16(_st + 1*BUFB + so0, pA0l + _k0);                                \
        cpa16(_st + 1*BUFB + so1, pA1l + _k0);                                \
        cpa16(_st + 2*BUFB + so0, pB0h + _k0);                                \
        cpa16(_st + 2*BUFB + so1, pB1h + _k0);                                \
        cpa16(_st + 3*BUFB + so0, pB0l + _k0);                                \
        cpa16(_st + 3*BUFB + so1, pB1l + _k0);                                \
        asm volatile("cp.async.commit_group;");                               \
    } while (0)

    ISSUE_IN(0, 0);

    for (int s = 0; s < NS; ++s) {
        if (s + 1 < NS) {
            ISSUE_IN(s + 1, (s + 1) & 1);
            asm volatile("cp.async.wait_group 1;");
        } else {
            asm volatile("cp.async.wait_group 0;");
        }
        __syncthreads();
        uint32_t soff = (uint32_t)(s & 1)*4*BUFB;
        uint32_t aAh = sbase + soff + 0*BUFB;
        uint32_t aAl = sbase + soff + 1*BUFB;
        uint32_t aBh = sbase + soff + 2*BUFB;
        uint32_t aBl = sbase + soff + 3*BUFB;
#pragma unroll
        for (int h = 0; h < 2; ++h) {
            int koff = h*16;
            uint32_t ah[2][4], al[2][4];
            {
                int mat = lid >> 3, rin = lid & 7;
                int arow = wm*32 + ((mat & 1) ? 8 : 0) + rin;
                int acol = koff + ((mat >> 1) ? 8 : 0);
#pragma unroll
                for (int mt = 0; mt < 2; ++mt) {
                    uint32_t off = ((arow + mt*16)*KP + acol)*2;
                    ldsm4(ah[mt][0], ah[mt][1], ah[mt][2], ah[mt][3], aAh + off);
                    ldsm4(al[mt][0], al[mt][1], al[mt][2], al[mt][3], aAl + off);
                }
            }
            {
                int mat = (lid >> 3) & 1, rin = lid & 7;
                int brow_base = wn*64 + rin;
                int bcol = koff + mat*8;
#pragma unroll
                for (int jt = 0; jt < 8; ++jt) {
                    uint32_t off = ((brow_base + jt*8)*KP + bcol)*2;
                    uint32_t bh[2], bl[2];
                    ldsm2(bh[0], bh[1], aBh + off);
                    ldsm2(bl[0], bl[1], aBl + off);
#pragma unroll
                    for (int mt = 0; mt < 2; ++mt) {
                        mma16816(acc[mt][jt], ah[mt], bh);
                        mma16816(acc[mt][jt], ah[mt], bl);
                        mma16816(acc[mt][jt], al[mt], bh);
                    }
                }
            }
        }
        __syncthreads();
    }
#undef ISSUE_IN

    int qr = lid >> 2, qc = lid & 3;
#pragma unroll
    for (int mt = 0; mt < 2; ++mt) {
#pragma unroll
        for (int jt = 0; jt < 8; ++jt) {
            int n = n0 + wn*64 + jt*8 + qc*2;
            int m_a = m0 + wm*32 + mt*16 + qr;
            int m_b = m_a + 8;
            float b0 = bias[n], b1 = bias[n+1];
            int ba = m_a >> 12, la = m_a & (L_-1);
            int bbv = m_b >> 12, lb = m_b & (L_-1);
            g_xt[((size_t)(ba*D_  + n  ))*L_ + la] = acc[mt][jt][0] + b0;
            g_xt[((size_t)(ba*D_  + n+1))*L_ + la] = acc[mt][jt][1] + b1;
            g_xt[((size_t)(bbv*D_ + n  ))*L_ + lb] = acc[mt][jt][2] + b0;
            g_xt[((size_t)(bbv*D_ + n+1))*L_ + lb] = acc[mt][jt][3] + b1;
        }
    }
}

// ======== k_mma_out: out_proj GEMM, A from [k][m] via ldmatrix.trans ========
#define KPA  136                 // A smem pitch (bf16): 128 data + 8 pad
#define ABUF (32*KPA*2)          // 8704 B per A buffer (32 k-rows x 128 m)
#define BBUF (128*KP*2)          // 10240 B per B buffer
#define STGB (2*ABUF + 2*BBUF)   // bytes per stage
#define SM_MO (2*STGB)           // 75776 B

__global__ __launch_bounds__(256) void k_mma_out(const float* __restrict__ outb,
                                                 float* __restrict__ out) {
    const int KDIM = CD_;
    uint32_t sbase = smem_u32(dynsmem);
    int tid = threadIdx.x, wid = tid >> 5, lid = tid & 31;
    int n0 = blockIdx.x*128, m0 = blockIdx.y*128;
    int wm = wid & 3, wn = wid >> 2;
    int bbm = m0 >> 12;                 // batch of this m-tile
    int l0  = m0 & (L_-1);

    float acc[2][8][4];
#pragma unroll
    for (int i = 0; i < 2; ++i)
#pragma unroll
        for (int j = 0; j < 8; ++j)
#pragma unroll
            for (int c = 0; c < 4; ++c) acc[i][j][c] = 0.f;

    // A: [k][m] rows; thread handles rows rA and rA+16, chunk cA
    int rA = tid >> 4, cA = tid & 15;
    const __nv_bfloat16* Ahb = g_yh + (size_t)bbm*CD_*L_ + l0;
    const __nv_bfloat16* Alb = g_yl + (size_t)bbm*CD_*L_ + l0;
    uint32_t soA0 = (rA*KPA + cA*8)*2;
    uint32_t soA1 = ((rA+16)*KPA + cA*8)*2;
    // B: [n][k] rows
    int r0i = tid >> 2, c0i = tid & 3;
    int r1i = r0i + 64;
    const __nv_bfloat16* pB0h = g_wt_hi + (size_t)(n0 + r0i)*KDIM + c0i*8;
    const __nv_bfloat16* pB1h = g_wt_hi + (size_t)(n0 + r1i)*KDIM + c0i*8;
    const __nv_bfloat16* pB0l = g_wt_lo + (size_t)(n0 + r0i)*KDIM + c0i*8;
    const __nv_bfloat16* pB1l = g_wt_lo + (size_t)(n0 + r1i)*KDIM + c0i*8;
    uint32_t soB0 = (r0i*KP + c0i*8)*2;
    uint32_t soB1 = (r1i*KP + c0i*8)*2;

    const int NS = KDIM/32;

#define ISSUE_OUT(s, stg) do {                                                \
        int _k0 = (s)*32;                                                     \
        uint32_t _st = sbase + (stg)*STGB;                                    \
        cpa16(_st + soA0,            Ahb + (size_t)(_k0 + rA)*L_ + cA*8);     \
        cpa16(_st + soA1,            Ahb + (size_t)(_k0 + rA + 16)*L_ + cA*8);\
        cpa16(_st + ABUF + soA0,     Alb + (size_t)(_k0 + rA)*L_ + cA*8);     \
        cpa16(_st + ABUF + soA1,     Alb + (size_t)(_k0 + rA + 16)*L_ + cA*8);\
        cpa16(_st + 2*ABUF + soB0,        pB0h + _k0);                        \
        cpa16(_st + 2*ABUF + soB1,        pB1h + _k0);                        \
        cpa16(_st + 2*ABUF + BBUF + soB0, pB0l + _k0);                        \
        cpa16(_st + 2*ABUF + BBUF + soB1, pB1l + _k0);                        \
        asm volatile("cp.async.commit_group;");                               \
    } while (0)

    ISSUE_OUT(0, 0);

    for (int s = 0; s < NS; ++s) {
        if (s + 1 < NS) {
            ISSUE_OUT(s + 1, (s + 1) & 1);
            asm volatile("cp.async.wait_group 1;");
        } else {
            asm volatile("cp.async.wait_group 0;");
        }
        __syncthreads();
        uint32_t soff = (uint32_t)(s & 1)*STGB;
        uint32_t aAh = sbase + soff;
        uint32_t aAl = sbase + soff + ABUF;
        uint32_t aBh = sbase + soff + 2*ABUF;
        uint32_t aBl = sbase + soff + 2*ABUF + BBUF;
#pragma unroll
        for (int h = 0; h < 2; ++h) {
            int koff = h*16;
            uint32_t ah[2][4], al[2][4];
            {
                int mat = lid >> 3, rin = lid & 7;
                int akrow = koff + ((mat >> 1) ? 8 : 0) + rin;
                int amcol = wm*32 + ((mat & 1) ? 8 : 0);
#pragma unroll
                for (int mt = 0; mt < 2; ++mt) {
                    uint32_t off = (akrow*KPA + amcol + mt*16)*2;
                    ldsm4t(ah[mt][0], ah[mt][1], ah[mt][2], ah[mt][3], aAh + off);
                    ldsm4t(al[mt][0], al[mt][1], al[mt][2], al[mt][3], aAl + off);
                }
            }
            {
                int mat = (lid >> 3) & 1, rin = lid & 7;
                int brow_base = wn*64 + rin;
                int bcol = koff + mat*8;
#pragma unroll
                for (int jt = 0; jt < 8; ++jt) {
                    uint32_t off = ((brow_base + jt*8)*KP + bcol)*2;
                    uint32_t bh[2], bl[2];
                    ldsm2(bh[0], bh[1], aBh + off);
                    ldsm2(bl[0], bl[1], aBl + off);
#pragma unroll
                    for (int mt = 0; mt < 2; ++mt) {
                        mma16816(acc[mt][jt], ah[mt], bh);
                        mma16816(acc[mt][jt], ah[mt], bl);
                        mma16816(acc[mt][jt], al[mt], bh);
                    }
                }
            }
        }
        __syncthreads();
    }
#undef ISSUE_OUT

    int qr = lid >> 2, qc = lid & 3;
#pragma unroll
    for (int mt = 0; mt < 2; ++mt) {
#pragma unroll
        for (int jt = 0; jt < 8; ++jt) {
            int n = n0 + wn*64 + jt*8 + qc*2;
            int m_a = m0 + wm*32 + mt*16 + qr;
            int m_b = m_a + 8;
            float b0 = outb[n], b1 = outb[n+1];
            int ba = m_a >> 12, la = m_a & (L_-1);
            int bbv = m_b >> 12, lb = m_b & (L_-1);
            float2 va = make_float2(acc[mt][jt][0] + b0, acc[mt][jt][1] + b1);
            float2 vb = make_float2(acc[mt][jt][2] + b0, acc[mt][jt][3] + b1);
            *(float2*)&out[((size_t)(ba*L_ + la))*D_ + n] = va;
            *(float2*)&out[((size_t)(bbv*L_ + lb))*D_ + n] = vb;
        }
    }
}

extern "C" void kernel_launch(void* const* d_in, const int* in_sizes, int n_in,
                              void* d_out, int out_size) {
    const float* u    = (const float*)d_in[0];
    const float* in_w = (const float*)d_in[1];
    const float* in_b = (const float*)d_in[2];
    const float* kern = (const float*)d_in[3];
    const float* dmat = (const float*)d_in[4];
    const float* outw = (const float*)d_in[5];
    const float* outb = (const float*)d_in[6];
    float* out = (float*)d_out;

    cudaFuncSetAttribute(k_fft_fwd,   cudaFuncAttributeMaxDynamicSharedMemorySize, SMEM_FFT);
    cudaFuncSetAttribute(k_conv_ifft, cudaFuncAttributeMaxDynamicSharedMemorySize, SMEM_FFT);
    cudaFuncSetAttribute(k_mma_out,   cudaFuncAttributeMaxDynamicSharedMemorySize, SM_MO);
    cudaFuncSetAttribute(k_mma_in,    cudaFuncAttributeMaxDynamicSharedMemorySize, SM_MMA);

    k_tw<<<(NFFT/2 + 255)/256, 256>>>();

    k_usplit<<<(B_*L_*D_/2)/256, 256>>>(u);
    { dim3 g(D_/32, D_/32);  k_w2tr<<<g, dim3(32,8)>>>(in_w); }
    { dim3 g(CD_/32, D_/32); k_wtr<<<g, dim3(32,8)>>>(outw); }

    { dim3 g(D_/128, (B_*L_)/128); k_mma_in<<<g, 256, SM_MMA>>>(in_b); }

    k_fft_fwd<<<B_*D_, 512, SMEM_FFT>>>(kern, 0);   // x rows
    k_fft_fwd<<<C_*D_, 512, SMEM_FFT>>>(kern, 1);   // kernel rows

    k_conv_ifft<<<B_*C_*D_, 512, SMEM_FFT>>>(dmat);

    { dim3 g(D_/128, (B_*L_)/128); k_mma_out<<<g, 256, SM_MO>>>(outb, out); }
}

// round 16
// speedup vs baseline: 1.0912x; 1.0062x over previous
#include <cuda_runtime.h>
#include <cuda_bf16.h>
#include <cstdint>
#include <math.h>

#define B_    2
#define L_    4096
#define D_    1024
#define C_    4
#define NFFT  8192          // conv length
#define N2    4096          // complex FFT length (real-packed)
#define LOG2N2 12
#define CD_   (C_*D_)

// XOR swizzle (bijective on [0,4096)); conflict-free for butterflies AND
// for the bit-reversed scatter writes.
#define SWZ(i) ((i) ^ (((i) >> 4) & 15) ^ (((i) >> 8) & 15))
#define BREV(i) ((int)(__brev((unsigned)(i)) >> 20))

// -------- scratch (device globals: allocation-free) --------
__device__ __align__(128) float  g_xt[B_*D_*L_];        // x transposed [b][d][l]
__device__ __align__(128) float2 g_Xf[B_*D_*N2];        // packed rfft of x rows
__device__ __align__(128) float2 g_Kf[C_*D_*N2];        // packed rfft of kernel rows
__device__ __align__(128) float2 g_tw[NFFT/2];          // e^{-2pi i k/8192}
// bf16 split conv output, [b][cd][l] (K-as-rows for trans-ldmatrix A)
__device__ __align__(128) __nv_bfloat16 g_yh[(size_t)B_*CD_*L_];
__device__ __align__(128) __nv_bfloat16 g_yl[(size_t)B_*CD_*L_];
// bf16 split operands for tensor-core GEMMs
__device__ __align__(128) __nv_bfloat16 g_wt_hi[D_*CD_];             // out_w^T [j][cd]
__device__ __align__(128) __nv_bfloat16 g_wt_lo[D_*CD_];
__device__ __align__(128) __nv_bfloat16 g_ut_hi[(size_t)B_*L_*D_];   // u split [b*L+l][d]
__device__ __align__(128) __nv_bfloat16 g_ut_lo[(size_t)B_*L_*D_];
__device__ __align__(128) __nv_bfloat16 g_w2_hi[D_*D_];              // in_w^T [n][k]
__device__ __align__(128) __nv_bfloat16 g_w2_lo[D_*D_];

// single dynamic smem symbol shared by all kernels
extern __shared__ char dynsmem[];

// -------- twiddle table --------
__global__ void k_tw() {
    int k = blockIdx.x*blockDim.x + threadIdx.x;
    if (k < NFFT/2) {
        double a = -2.0*M_PI*(double)k/(double)NFFT;
        g_tw[k] = make_float2((float)cos(a), (float)sin(a));
    }
}

// -------- split u into bf16 hi/lo (already K-major) --------
__global__ __launch_bounds__(256) void k_usplit(const float* __restrict__ u) {
    size_t e = ((size_t)blockIdx.x*blockDim.x + threadIdx.x)*2;
    float2 v = *(const float2*)&u[e];
    __nv_bfloat16 h0 = __float2bfloat16(v.x);
    __nv_bfloat16 h1 = __float2bfloat16(v.y);
    __nv_bfloat16 l0 = __float2bfloat16(v.x - __bfloat162float(h0));
    __nv_bfloat16 l1 = __float2bfloat16(v.y - __bfloat162float(h1));
    __nv_bfloat162 hh; hh.x = h0; hh.y = h1;
    __nv_bfloat162 ll; ll.x = l0; ll.y = l1;
    *(__nv_bfloat162*)&g_ut_hi[e] = hh;
    *(__nv_bfloat162*)&g_ut_lo[e] = ll;
}

// -------- transpose + split in_w [k][n] -> [n][k] --------
__global__ __launch_bounds__(256) void k_w2tr(const float* __restrict__ inw) {
    __shared__ float t[32][33];
    int k0 = blockIdx.x*32, j0 = blockIdx.y*32;
    int tx = threadIdx.x, ty = threadIdx.y;
#pragma unroll
    for (int r = 0; r < 32; r += 8)
        t[ty+r][tx] = inw[(size_t)(k0+ty+r)*D_ + j0+tx];
    __syncthreads();
#pragma unroll
    for (int r = 0; r < 32; r += 8) {
        float v = t[tx][ty+r];
        __nv_bfloat16 h = __float2bfloat16(v);
        __nv_bfloat16 lo = __float2bfloat16(v - __bfloat162float(h));
        size_t o = (size_t)(j0+ty+r)*D_ + k0+tx;
        g_w2_hi[o] = h; g_w2_lo[o] = lo;
    }
}

// -------- transpose + split out_w [cd][j] -> [j][cd] --------
__global__ __launch_bounds__(256) void k_wtr(const float* __restrict__ outw) {
    __shared__ float t[32][33];
    int k0 = blockIdx.x*32, j0 = blockIdx.y*32;
    int tx = threadIdx.x, ty = threadIdx.y;
#pragma unroll
    for (int r = 0; r < 32; r += 8)
        t[ty+r][tx] = outw[(size_t)(k0+ty+r)*D_ + j0+tx];
    __syncthreads();
#pragma unroll
    for (int r = 0; r < 32; r += 8) {
        float v = t[tx][ty+r];
        __nv_bfloat16 h = __float2bfloat16(v);
        __nv_bfloat16 lo = __float2bfloat16(v - __bfloat162float(h));
        size_t o = (size_t)(j0+ty+r)*CD_ + k0+tx;
        g_wt_hi[o] = h; g_wt_lo[o] = lo;
    }
}

// ======== radix-8-fused FFT on N2=4096 complex points in shared ========
// Input must ALREADY be at bit-reversed (SWZ'd) positions; output natural.
// FHZ: upper half of natural input is zero -> odd brev slots are zero and
// never written; first pass synthesizes them (b=0 butterfly => copy).
__device__ __forceinline__ void bf2(float2& a, float2& b, float2 w, bool inv) {
    float wy = inv ? -w.y : w.y;
    float brx = b.x*w.x - b.y*wy;
    float bry = b.x*wy + b.y*w.x;
    b.x = a.x - brx; b.y = a.y - bry;
    a.x += brx;      a.y += bry;
}

// requires blockDim.x == 512; caller must __syncthreads() before calling
template<bool FHZ>
__device__ __forceinline__ void block_fft(float2* s, int tid, bool inv) {
#pragma unroll
    for (int sp = 0; sp < LOG2N2; sp += 3) {
        int half = 1 << sp;
        int pos  = tid & (half - 1);
        int base = ((tid >> sp) << (sp + 3)) | pos;
        float2 v[8];
        if (FHZ && sp == 0) {
            // only even slots hold data; stage A degenerates to copy
            v[0] = s[SWZ(base + 0)];
            v[2] = s[SWZ(base + 2)];
            v[4] = s[SWZ(base + 4)];
            v[6] = s[SWZ(base + 6)];
            v[1] = v[0]; v[3] = v[2]; v[5] = v[4]; v[7] = v[6];
        } else {
#pragma unroll
            for (int q = 0; q < 8; ++q) v[q] = s[SWZ(base + q*half)];
            int stepA = NFFT >> (sp + 1);
            float2 wA = __ldg(&g_tw[pos*stepA]);
            bf2(v[0], v[1], wA, inv); bf2(v[2], v[3], wA, inv);
            bf2(v[4], v[5], wA, inv); bf2(v[6], v[7], wA, inv);
        }
        int stepB = NFFT >> (sp + 2);
        int stepC = NFFT >> (sp + 3);
        float2 wB0 = __ldg(&g_tw[pos*stepB]), wB1 = __ldg(&g_tw[(pos+half)*stepB]);
        bf2(v[0], v[2], wB0, inv); bf2(v[1], v[3], wB1, inv);
        bf2(v[4], v[6], wB0, inv); bf2(v[5], v[7], wB1, inv);
        float2 wC0 = __ldg(&g_tw[pos*stepC]),        wC1 = __ldg(&g_tw[(pos+half)*stepC]);
        float2 wC2 = __ldg(&g_tw[(pos+2*half)*stepC]), wC3 = __ldg(&g_tw[(pos+3*half)*stepC]);
        bf2(v[0], v[4], wC0, inv); bf2(v[1], v[5], wC1, inv);
        bf2(v[2], v[6], wC2, inv); bf2(v[3], v[7], wC3, inv);
#pragma unroll
        for (int q = 0; q < 8; ++q) s[SWZ(base + q*half)] = v[q];
        __syncthreads();
    }
}

#define SMEM_FFT (N2 * (int)sizeof(float2))   // 32 KB data only

__device__ __forceinline__ float2 ldcs2(const float2* p) {
    float2 r;
    asm volatile("ld.global.cs.v2.f32 {%0,%1}, [%2];" : "=f"(r.x), "=f"(r.y) : "l"(p));
    return r;
}

// -------- forward rfft of real rows (x rows then kernel rows, one grid) ----
// blocks [0, B*D) -> x rows from g_xt -> g_Xf
// blocks [B*D, B*D + C*D) -> kernel rows -> g_Kf
__global__ __launch_bounds__(512) void k_fft_fwd(const float* __restrict__ kern) {
    float2* s = (float2*)dynsmem;
    int tid = threadIdx.x, bs = blockDim.x;
    int blk = blockIdx.x;
    int mode = (blk >= B_*D_);
    size_t row = mode ? (size_t)(blk - B_*D_) : (size_t)blk;
    const float* src = mode ? (kern + row*L_) : (g_xt + row*L_);
    // only natural m < 2048 (even brev slots); odd slots never read (FHZ)
    for (int m = tid; m < L_/2; m += bs)
        s[SWZ(BREV(m))] = ldcs2((const float2*)&src[2*m]);
    __syncthreads();
    block_fft<true>(s, tid, false);
    float2* dst = (mode ? g_Kf : g_Xf) + row*(size_t)N2;
    for (int k = tid; k < N2; k += bs) {
        if (k == 0) {
            float2 z0 = s[SWZ(0)];
            dst[0] = make_float2(z0.x + z0.y, z0.x - z0.y);
        } else {
            float2 A = s[SWZ(k)], Bm = s[SWZ(N2 - k)];
            float2 E = make_float2(0.5f*(A.x + Bm.x), 0.5f*(A.y - Bm.y));
            float2 O = make_float2(0.5f*(A.y + Bm.y), -0.5f*(A.x - Bm.x));
            float2 w = __ldg(&g_tw[k]);
            dst[k] = make_float2(E.x + w.x*O.x - w.y*O.y,
                                 E.y + w.x*O.y + w.y*O.x);
        }
    }
}

// ---- spectrum product (dmat folded: K' = K + dsc) fused with inverse
// Hermitian pack (brev scatter) + inverse FFT + bf16 split epilogue ----
// block decode: cd = idx>>1, bb = idx&1 (adjacent pair shares kf row)
__global__ __launch_bounds__(512) void k_conv_ifft(const float* __restrict__ dmat) {
    float2* s = (float2*)dynsmem;
    int tid = threadIdx.x, bs = blockDim.x;
    int idx = blockIdx.x;
    int cd = idx >> 1;
    int bb = idx & 1;
    int d  = cd & (D_-1);
    const float2* xf = g_Xf + ((size_t)(bb*D_ + d))*N2;
    const float2* kf = g_Kf + (size_t)cd*N2;
    float dsc = __ldg(&dmat[cd]);
    for (int k = tid; k < N2/2; k += bs) {
        if (k == 0) {
            float2 a0 = ldcs2(&xf[0]), b0 = __ldg(&kf[0]);
            float y0 = a0.x*(b0.x + dsc), yn = a0.y*(b0.y + dsc);
            s[SWZ(0)] = make_float2(0.5f*(y0 + yn), 0.5f*(y0 - yn));   // BREV(0)=0
            float2 ah = ldcs2(&xf[N2/2]), bh = __ldg(&kf[N2/2]);
            bh.x += dsc;
            float2 Yh = make_float2(ah.x*bh.x - ah.y*bh.y, ah.x*bh.y + ah.y*bh.x);
            s[SWZ(1)] = make_float2(Yh.x, -Yh.y);                       // BREV(N2/2)=1
        } else {
            float2 a  = ldcs2(&xf[k]),      b  = __ldg(&kf[k]);
            float2 a2 = ldcs2(&xf[N2 - k]), b2 = __ldg(&kf[N2 - k]);
            b.x += dsc; b2.x += dsc;
            float2 Yk = make_float2(a.x*b.x - a.y*b.y,   a.x*b.y + a.y*b.x);
            float2 Ym = make_float2(a2.x*b2.x - a2.y*b2.y, a2.x*b2.y + a2.y*b2.x);
            float2 E  = make_float2(0.5f*(Yk.x + Ym.x), 0.5f*(Yk.y - Ym.y));
            float2 Ow = make_float2(0.5f*(Yk.x - Ym.x), 0.5f*(Yk.y + Ym.y));
            float2 w = __ldg(&g_tw[k]);
            float2 O = make_float2(Ow.x*w.x + Ow.y*w.y, Ow.y*w.x - Ow.x*w.y);
            s[SWZ(BREV(k))]      = make_float2(E.x - O.y,  E.y + O.x);
            s[SWZ(BREV(N2 - k))] = make_float2(E.x + O.y, -E.y + O.x);
        }
    }
    __syncthreads();
    block_fft<false>(s, tid, true);
    size_t orow = (size_t)(bb*CD_ + cd)*L_;
    __nv_bfloat162* yh = (__nv_bfloat162*)(g_yh + orow);
    __nv_bfloat162* yl = (__nv_bfloat162*)(g_yl + orow);
    const float invn = 1.0f/(float)N2;
    for (int m = tid; m < L_/2; m += bs) {
        float2 z = s[SWZ(m)];
        float ox = z.x*invn;
        float oy = z.y*invn;
        __nv_bfloat16 h0 = __float2bfloat16(ox);
        __nv_bfloat16 h1 = __float2bfloat16(oy);
        __nv_bfloat16 l0 = __float2bfloat16(ox - __bfloat162float(h0));
        __nv_bfloat16 l1 = __float2bfloat16(oy - __bfloat162float(h1));
        __nv_bfloat162 hh; hh.x = h0; hh.y = h1;
        __nv_bfloat162 ll; ll.x = l0; ll.y = l1;
        yh[m] = hh;
        yl[m] = ll;
    }
}

// ======== mma.sync bf16 split GEMM machinery ========
#define KP 40   // smem row pitch (bf16): 32 data + 8 pad
#define BUFE (128*KP)            // elements per buffer
#define BUFB (BUFE*2)            // bytes per buffer
#define SM_MMA (2*4*BUFB)        // 2 stages x 4 buffers = 81920 B

__device__ __forceinline__ uint32_t smem_u32(const void* p) {
    uint32_t a;
    asm("{ .reg .u64 t; cvta.to.shared.u64 t, %1; cvt.u32.u64 %0, t; }" : "=r"(a) : "l"(p));
    return a;
}
__device__ __forceinline__ void cpa16(uint32_t saddr, const void* g) {
    asm volatile("cp.async.cg.shared.global [%0], [%1], 16;" :: "r"(saddr), "l"(g));
}
__device__ __forceinline__ void ldsm4(uint32_t& r0, uint32_t& r1, uint32_t& r2,
                                      uint32_t& r3, uint32_t addr) {
    asm volatile("ldmatrix.sync.aligned.m8n8.x4.shared.b16 {%0,%1,%2,%3}, [%4];"
                 : "=r"(r0), "=r"(r1), "=r"(r2), "=r"(r3) : "r"(addr));
}
__device__ __forceinline__ void ldsm4t(uint32_t& r0, uint32_t& r1, uint32_t& r2,
                                       uint32_t& r3, uint32_t addr) {
    asm volatile("ldmatrix.sync.aligned.m8n8.x4.trans.shared.b16 {%0,%1,%2,%3}, [%4];"
                 : "=r"(r0), "=r"(r1), "=r"(r2), "=r"(r3) : "r"(addr));
}
__device__ __forceinline__ void ldsm2(uint32_t& r0, uint32_t& r1, uint32_t addr) {
    asm volatile("ldmatrix.sync.aligned.m8n8.x2.shared.b16 {%0,%1}, [%2];"
                 : "=r"(r0), "=r"(r1) : "r"(addr));
}
__device__ __forceinline__ void mma16816(float* d, const uint32_t* a, const uint32_t* b) {
    asm volatile(
        "mma.sync.aligned.m16n8k16.row.col.f32.bf16.bf16.f32 "
        "{%0,%1,%2,%3}, {%4,%5,%6,%7}, {%8,%9}, {%0,%1,%2,%3};"
        : "+f"(d[0]), "+f"(d[1]), "+f"(d[2]), "+f"(d[3])
        : "r"(a[0]), "r"(a[1]), "r"(a[2]), "r"(a[3]), "r"(b[0]), "r"(b[1]));
}

// ======== k_mma_in: in_proj GEMM (A row-major [m][k]) ======
__global__ __launch_bounds__(256) void k_mma_in(const float* __restrict__ bias) {
    const int KDIM = D_;
    uint32_t sbase = smem_u32(dynsmem);
    int tid = threadIdx.x, wid = tid >> 5, lid = tid & 31;
    int n0 = blockIdx.x*128, m0 = blockIdx.y*128;
    int wm = wid & 3, wn = wid >> 2;

    float acc[2][8][4];
#pragma unroll
    for (int i = 0; i < 2; ++i)
#pragma unroll
        for (int j = 0; j < 8; ++j)
#pragma unroll
            for (int c = 0; c < 4; ++c) acc[i][j][c] = 0.f;

    int r0i = tid >> 2, c0i = tid & 3;
    int r1i = r0i + 64;
    const __nv_bfloat16* pA0h = g_ut_hi + (size_t)(m0 + r0i)*KDIM + c0i*8;
    const __nv_bfloat16* pA1h = g_ut_hi + (size_t)(m0 + r1i)*KDIM + c0i*8;
    const __nv_bfloat16* pA0l = g_ut_lo + (size_t)(m0 + r0i)*KDIM + c0i*8;
    const __nv_bfloat16* pA1l = g_ut_lo + (size_t)(m0 + r1i)*KDIM + c0i*8;
    const __nv_bfloat16* pB0h = g_w2_hi + (size_t)(n0 + r0i)*KDIM + c0i*8;
    const __nv_bfloat16* pB1h = g_w2_hi + (size_t)(n0 + r1i)*KDIM + c0i*8;
    const __nv_bfloat16* pB0l = g_w2_lo + (size_t)(n0 + r0i)*KDIM + c0i*8;
    const __nv_bfloat16* pB1l = g_w2_lo + (size_t)(n0 + r1i)*KDIM + c0i*8;
    uint32_t so0 = (r0i*KP + c0i*8)*2;
    uint32_t so1 = (r1i*KP + c0i*8)*2;

    const int NS = KDIM/32;

#define ISSUE_IN(s, stg) do {                                                 \
        int _k0 = (s)*32;                                                     \
        uint32_t _st = sbase + (stg)*4*BUFB;                                  \
        cpa16(_st + 0*BUFB + so0, pA0h + _k0);                                \
        cpa16(_st + 0*BUFB + so1, pA1h + _k0);                                \
        cpa16(_st + 1*BUFB + so0, pA0l + _k0);                                \
        cpa16(_st + 1*BUFB + so1, pA1l + _k0);                                \
        cpa16(_st + 2*BUFB + so0, pB0h + _k0);                                \
        cpa16(_st + 2*BUFB + so1, pB1h + _k0);                                \
        cpa16(_st + 3*BUFB + so0, pB0l + _k0);                                \
        cpa16(_st + 3*BUFB + so1, pB1l + _k0);                                \
        asm volatile("cp.async.commit_group;");                               \
    } while (0)

    ISSUE_IN(0, 0);

    for (int s = 0; s < NS; ++s) {
        if (s + 1 < NS) {
            ISSUE_IN(s + 1, (s + 1) & 1);
            asm volatile("cp.async.wait_group 1;");
        } else {
            asm volatile("cp.async.wait_group 0;");
        }
        __syncthreads();
        uint32_t soff = (uint32_t)(s & 1)*4*BUFB;
        uint32_t aAh = sbase + soff + 0*BUFB;
        uint32_t aAl = sbase + soff + 1*BUFB;
        uint32_t aBh = sbase + soff + 2*BUFB;
        uint32_t aBl = sbase + soff + 3*BUFB;
#pragma unroll
        for (int h = 0; h < 2; ++h) {
            int koff = h*16;
            uint32_t ah[2][4], al[2][4];
            {
                int mat = lid >> 3, rin = lid & 7;
                int arow = wm*32 + ((mat & 1) ? 8 : 0) + rin;
                int acol = koff + ((mat >> 1) ? 8 : 0);
#pragma unroll
                for (int mt = 0; mt < 2; ++mt) {
                    uint32_t off = ((arow + mt*16)*KP + acol)*2;
                    ldsm4(ah[mt][0], ah[mt][1], ah[mt][2], ah[mt][3], aAh + off);
                    ldsm4(al[mt][0], al[mt][1], al[mt][2], al[mt][3], aAl + off);
                }
            }
            {
                int mat = (lid >> 3) & 1, rin = lid & 7;
                int brow_base = wn*64 + rin;
                int bcol = koff + mat*8;
#pragma unroll
                for (int jt = 0; jt < 8; ++jt) {
                    uint32_t off = ((brow_base + jt*8)*KP + bcol)*2;
                    uint32_t bh[2], bl[2];
                    ldsm2(bh[0], bh[1], aBh + off);
                    ldsm2(bl[0], bl[1], aBl + off);
#pragma unroll
                    for (int mt = 0; mt < 2; ++mt) {
                        mma16816(acc[mt][jt], ah[mt], bh);
                        mma16816(acc[mt][jt], ah[mt], bl);
                        mma16816(acc[mt][jt], al[mt], bh);
                    }
                }
            }
        }
        __syncthreads();
    }
#undef ISSUE_IN

    int qr = lid >> 2, qc = lid & 3;
#pragma unroll
    for (int mt = 0; mt < 2; ++mt) {
#pragma unroll
        for (int jt = 0; jt < 8; ++jt) {
            int n = n0 + wn*64 + jt*8 + qc*2;
            int m_a = m0 + wm*32 + mt*16 + qr;
            int m_b = m_a + 8;
            float b0 = bias[n], b1 = bias[n+1];
            int ba = m_a >> 12, la = m_a & (L_-1);
            int bbv = m_b >> 12, lb = m_b & (L_-1);
            g_xt[((size_t)(ba*D_  + n  ))*L_ + la] = acc[mt][jt][0] + b0;
            g_xt[((size_t)(ba*D_  + n+1))*L_ + la] = acc[mt][jt][1] + b1;
            g_xt[((size_t)(bbv*D_ + n  ))*L_ + lb] = acc[mt][jt][2] + b0;
            g_xt[((size_t)(bbv*D_ + n+1))*L_ + lb] = acc[mt][jt][3] + b1;
        }
    }
}

// ======== k_mma_out: out_proj GEMM, A from [k][m] via ldmatrix.trans ========
#define KPA  136                 // A smem pitch (bf16): 128 data + 8 pad
#define ABUF (32*KPA*2)          // 8704 B per A buffer (32 k-rows x 128 m)
#define BBUF (128*KP*2)          // 10240 B per B buffer
#define STGB (2*ABUF + 2*BBUF)   // bytes per stage
#define SM_MO (2*STGB)           // 75776 B

__global__ __launch_bounds__(256) void k_mma_out(const float* __restrict__ outb,
                                                 float* __restrict__ out) {
    const int KDIM = CD_;
    uint32_t sbase = smem_u32(dynsmem);
    int tid = threadIdx.x, wid = tid >> 5, lid = tid & 31;
    int n0 = blockIdx.x*128, m0 = blockIdx.y*128;
    int wm = wid & 3, wn = wid >> 2;
    int bbm = m0 >> 12;                 // batch of this m-tile
    int l0  = m0 & (L_-1);

    float acc[2][8][4];
#pragma unroll
    for (int i = 0; i < 2; ++i)
#pragma unroll
        for (int j = 0; j < 8; ++j)
#pragma unroll
            for (int c = 0; c < 4; ++c) acc[i][j][c] = 0.f;

    // A: [k][m] rows; thread handles rows rA and rA+16, chunk cA
    int rA = tid >> 4, cA = tid & 15;
    const __nv_bfloat16* Ahb = g_yh + (size_t)bbm*CD_*L_ + l0;
    const __nv_bfloat16* Alb = g_yl + (size_t)bbm*CD_*L_ + l0;
    uint32_t soA0 = (rA*KPA + cA*8)*2;
    uint32_t soA1 = ((rA+16)*KPA + cA*8)*2;
    // B: [n][k] rows
    int r0i = tid >> 2, c0i = tid & 3;
    int r1i = r0i + 64;
    const __nv_bfloat16* pB0h = g_wt_hi + (size_t)(n0 + r0i)*KDIM + c0i*8;
    const __nv_bfloat16* pB1h = g_wt_hi + (size_t)(n0 + r1i)*KDIM + c0i*8;
    const __nv_bfloat16* pB0l = g_wt_lo + (size_t)(n0 + r0i)*KDIM + c0i*8;
    const __nv_bfloat16* pB1l = g_wt_lo + (size_t)(n0 + r1i)*KDIM + c0i*8;
    uint32_t soB0 = (r0i*KP + c0i*8)*2;
    uint32_t soB1 = (r1i*KP + c0i*8)*2;

    const int NS = KDIM/32;

#define ISSUE_OUT(s, stg) do {                                                \
        int _k0 = (s)*32;                                                     \
        uint32_t _st = sbase + (stg)*STGB;                                    \
        cpa16(_st + soA0,            Ahb + (size_t)(_k0 + rA)*L_ + cA*8);     \
        cpa16(_st + soA1,            Ahb + (size_t)(_k0 + rA + 16)*L_ + cA*8);\
        cpa16(_st + ABUF + soA0,     Alb + (size_t)(_k0 + rA)*L_ + cA*8);     \
        cpa16(_st + ABUF + soA1,     Alb + (size_t)(_k0 + rA + 16)*L_ + cA*8);\
        cpa16(_st + 2*ABUF + soB0,        pB0h + _k0);                        \
        cpa16(_st + 2*ABUF + soB1,        pB1h + _k0);                        \
        cpa16(_st + 2*ABUF + BBUF + soB0, pB0l + _k0);                        \
        cpa16(_st + 2*ABUF + BBUF + soB1, pB1l + _k0);                        \
        asm volatile("cp.async.commit_group;");                               \
    } while (0)

    ISSUE_OUT(0, 0);

    for (int s = 0; s < NS; ++s) {
        if (s + 1 < NS) {
            ISSUE_OUT(s + 1, (s + 1) & 1);
            asm volatile("cp.async.wait_group 1;");
        } else {
            asm volatile("cp.async.wait_group 0;");
        }
        __syncthreads();
        uint32_t soff = (uint32_t)(s & 1)*STGB;
        uint32_t aAh = sbase + soff;
        uint32_t aAl = sbase + soff + ABUF;
        uint32_t aBh = sbase + soff + 2*ABUF;
        uint32_t aBl = sbase + soff + 2*ABUF + BBUF;
#pragma unroll
        for (int h = 0; h < 2; ++h) {
            int koff = h*16;
            uint32_t ah[2][4], al[2][4];
            {
                int mat = lid >> 3, rin = lid & 7;
                int akrow = koff + ((mat >> 1) ? 8 : 0) + rin;
                int amcol = wm*32 + ((mat & 1) ? 8 : 0);
#pragma unroll
                for (int mt = 0; mt < 2; ++mt) {
                    uint32_t off = (akrow*KPA + amcol + mt*16)*2;
                    ldsm4t(ah[mt][0], ah[mt][1], ah[mt][2], ah[mt][3], aAh + off);
                    ldsm4t(al[mt][0], al[mt][1], al[mt][2], al[mt][3], aAl + off);
                }
            }
            {
                int mat = (lid >> 3) & 1, rin = lid & 7;
                int brow_base = wn*64 + rin;
                int bcol = koff + mat*8;
#pragma unroll
                for (int jt = 0; jt < 8; ++jt) {
                    uint32_t off = ((brow_base + jt*8)*KP + bcol)*2;
                    uint32_t bh[2], bl[2];
                    ldsm2(bh[0], bh[1], aBh + off);
                    ldsm2(bl[0], bl[1], aBl + off);
#pragma unroll
                    for (int mt = 0; mt < 2; ++mt) {
                        mma16816(acc[mt][jt], ah[mt], bh);
                        mma16816(acc[mt][jt], ah[mt], bl);
                        mma16816(acc[mt][jt], al[mt], bh);
                    }
                }
            }
        }
        __syncthreads();
    }
#undef ISSUE_OUT

    int qr = lid >> 2, qc = lid & 3;
#pragma unroll
    for (int mt = 0; mt < 2; ++mt) {
#pragma unroll
        for (int jt = 0; jt < 8; ++jt) {
            int n = n0 + wn*64 + jt*8 + qc*2;
            int m_a = m0 + wm*32 + mt*16 + qr;
            int m_b = m_a + 8;
            float b0 = outb[n], b1 = outb[n+1];
            int ba = m_a >> 12, la = m_a & (L_-1);
            int bbv = m_b >> 12, lb = m_b & (L_-1);
            float2 va = make_float2(acc[mt][jt][0] + b0, acc[mt][jt][1] + b1);
            float2 vb = make_float2(acc[mt][jt][2] + b0, acc[mt][jt][3] + b1);
            *(float2*)&out[((size_t)(ba*L_ + la))*D_ + n] = va;
            *(float2*)&out[((size_t)(bbv*L_ + lb))*D_ + n] = vb;
        }
    }
}

extern "C" void kernel_launch(void* const* d_in, const int* in_sizes, int n_in,
                              void* d_out, int out_size) {
    const float* u    = (const float*)d_in[0];
    const float* in_w = (const float*)d_in[1];
    const float* in_b = (const float*)d_in[2];
    const float* kern = (const float*)d_in[3];
    const float* dmat = (const float*)d_in[4];
    const float* outw = (const float*)d_in[5];
    const float* outb = (const float*)d_in[6];
    float* out = (float*)d_out;

    cudaFuncSetAttribute(k_fft_fwd,   cudaFuncAttributeMaxDynamicSharedMemorySize, SMEM_FFT);
    cudaFuncSetAttribute(k_conv_ifft, cudaFuncAttributeMaxDynamicSharedMemorySize, SMEM_FFT);
    cudaFuncSetAttribute(k_mma_out,   cudaFuncAttributeMaxDynamicSharedMemorySize, SM_MO);
    cudaFuncSetAttribute(k_mma_in,    cudaFuncAttributeMaxDynamicSharedMemorySize, SM_MMA);

    k_tw<<<(NFFT/2 + 255)/256, 256>>>();

    k_usplit<<<(B_*L_*D_/2)/256, 256>>>(u);
    { dim3 g(D_/32, D_/32);  k_w2tr<<<g, dim3(32,8)>>>(in_w); }
    { dim3 g(CD_/32, D_/32); k_wtr<<<g, dim3(32,8)>>>(outw); }

    { dim3 g(D_/128, (B_*L_)/128); k_mma_in<<<g, 256, SM_MMA>>>(in_b); }

    k_fft_fwd<<<B_*D_ + C_*D_, 512, SMEM_FFT>>>(kern);   // x rows + kernel rows

    k_conv_ifft<<<B_*C_*D_, 512, SMEM_FFT>>>(dmat);

    { dim3 g(D_/128, (B_*L_)/128); k_mma_out<<<g, 256, SM_MO>>>(outb, out); }
}

// round 17
// speedup vs baseline: 1.0931x; 1.0017x over previous
#include <cuda_runtime.h>
#include <cuda_bf16.h>
#include <cstdint>
#include <math.h>

#define B_    2
#define L_    4096
#define D_    1024
#define C_    4
#define NFFT  8192          // conv length
#define N2    4096          // complex FFT length (real-packed)
#define LOG2N2 12
#define CD_   (C_*D_)

// XOR swizzle (bijective on [0,4096)); conflict-free for butterflies AND
// for the bit-reversed scatter writes.
#define SWZ(i) ((i) ^ (((i) >> 4) & 15) ^ (((i) >> 8) & 15))
#define BREV(i) ((int)(__brev((unsigned)(i)) >> 20))

// -------- scratch (device globals: allocation-free) --------
__device__ __align__(128) float  g_xt[B_*D_*L_];        // x transposed [b][d][l]
__device__ __align__(128) float2 g_Xf[B_*D_*N2];        // packed rfft of x rows
__device__ __align__(128) float2 g_Kf[C_*D_*N2];        // packed rfft of kernel rows
__device__ __align__(128) float2 g_tw[NFFT/2];          // e^{-2pi i k/8192}
// bf16 split conv output, [b][cd][l] (K-as-rows for trans-ldmatrix A)
__device__ __align__(128) __nv_bfloat16 g_yh[(size_t)B_*CD_*L_];
__device__ __align__(128) __nv_bfloat16 g_yl[(size_t)B_*CD_*L_];
// bf16 split operands for tensor-core GEMMs
__device__ __align__(128) __nv_bfloat16 g_wt_hi[D_*CD_];             // out_w^T [j][cd]
__device__ __align__(128) __nv_bfloat16 g_wt_lo[D_*CD_];
__device__ __align__(128) __nv_bfloat16 g_ut_hi[(size_t)B_*L_*D_];   // u split [b*L+l][d]
__device__ __align__(128) __nv_bfloat16 g_ut_lo[(size_t)B_*L_*D_];
__device__ __align__(128) __nv_bfloat16 g_w2_hi[D_*D_];              // in_w^T [n][k]
__device__ __align__(128) __nv_bfloat16 g_w2_lo[D_*D_];

// single dynamic smem symbol shared by all kernels
extern __shared__ char dynsmem[];

// -------- streams/events for graph fork-join (created once, pre-main) -----
static cudaStream_t s_str1, s_str2;
static cudaEvent_t  s_evRoot, s_evTw, s_evK, s_evW;
namespace {
struct StreamInit {
    StreamInit() {
        cudaStreamCreateWithFlags(&s_str1, cudaStreamNonBlocking);
        cudaStreamCreateWithFlags(&s_str2, cudaStreamNonBlocking);
        cudaEventCreateWithFlags(&s_evRoot, cudaEventDisableTiming);
        cudaEventCreateWithFlags(&s_evTw,   cudaEventDisableTiming);
        cudaEventCreateWithFlags(&s_evK,    cudaEventDisableTiming);
        cudaEventCreateWithFlags(&s_evW,    cudaEventDisableTiming);
    }
};
StreamInit s_streamInit;
}

// -------- twiddle table --------
__global__ void k_tw() {
    int k = blockIdx.x*blockDim.x + threadIdx.x;
    if (k < NFFT/2) {
        double a = -2.0*M_PI*(double)k/(double)NFFT;
        g_tw[k] = make_float2((float)cos(a), (float)sin(a));
    }
}

// -------- split u into bf16 hi/lo (already K-major) --------
__global__ __launch_bounds__(256) void k_usplit(const float* __restrict__ u) {
    size_t e = ((size_t)blockIdx.x*blockDim.x + threadIdx.x)*2;
    float2 v = *(const float2*)&u[e];
    __nv_bfloat16 h0 = __float2bfloat16(v.x);
    __nv_bfloat16 h1 = __float2bfloat16(v.y);
    __nv_bfloat16 l0 = __float2bfloat16(v.x - __bfloat162float(h0));
    __nv_bfloat16 l1 = __float2bfloat16(v.y - __bfloat162float(h1));
    __nv_bfloat162 hh; hh.x = h0; hh.y = h1;
    __nv_bfloat162 ll; ll.x = l0; ll.y = l1;
    *(__nv_bfloat162*)&g_ut_hi[e] = hh;
    *(__nv_bfloat162*)&g_ut_lo[e] = ll;
}

// -------- transpose + split in_w [k][n] -> [n][k] --------
__global__ __launch_bounds__(256) void k_w2tr(const float* __restrict__ inw) {
    __shared__ float t[32][33];
    int k0 = blockIdx.x*32, j0 = blockIdx.y*32;
    int tx = threadIdx.x, ty = threadIdx.y;
#pragma unroll
    for (int r = 0; r < 32; r += 8)
        t[ty+r][tx] = inw[(size_t)(k0+ty+r)*D_ + j0+tx];
    __syncthreads();
#pragma unroll
    for (int r = 0; r < 32; r += 8) {
        float v = t[tx][ty+r];
        __nv_bfloat16 h = __float2bfloat16(v);
        __nv_bfloat16 lo = __float2bfloat16(v - __bfloat162float(h));
        size_t o = (size_t)(j0+ty+r)*D_ + k0+tx;
        g_w2_hi[o] = h; g_w2_lo[o] = lo;
    }
}

// -------- transpose + split out_w [cd][j] -> [j][cd] --------
__global__ __launch_bounds__(256) void k_wtr(const float* __restrict__ outw) {
    __shared__ float t[32][33];
    int k0 = blockIdx.x*32, j0 = blockIdx.y*32;
    int tx = threadIdx.x, ty = threadIdx.y;
#pragma unroll
    for (int r = 0; r < 32; r += 8)
        t[ty+r][tx] = outw[(size_t)(k0+ty+r)*D_ + j0+tx];
    __syncthreads();
#pragma unroll
    for (int r = 0; r < 32; r += 8) {
        float v = t[tx][ty+r];
        __nv_bfloat16 h = __float2bfloat16(v);
        __nv_bfloat16 lo = __float2bfloat16(v - __bfloat162float(h));
        size_t o = (size_t)(j0+ty+r)*CD_ + k0+tx;
        g_wt_hi[o] = h; g_wt_lo[o] = lo;
    }
}

// ======== radix-8-fused FFT on N2=4096 complex points in shared ========
// Input must ALREADY be at bit-reversed (SWZ'd) positions; output natural.
// FHZ: upper half of natural input is zero -> odd brev slots are zero and
// never written; first pass synthesizes them (b=0 butterfly => copy).
__device__ __forceinline__ void bf2(float2& a, float2& b, float2 w, bool inv) {
    float wy = inv ? -w.y : w.y;
    float brx = b.x*w.x - b.y*wy;
    float bry = b.x*wy + b.y*w.x;
    b.x = a.x - brx; b.y = a.y - bry;
    a.x += brx;      a.y += bry;
}

// requires blockDim.x == 512; caller must __syncthreads() before calling
template<bool FHZ>
__device__ __forceinline__ void block_fft(float2* s, int tid, bool inv) {
#pragma unroll
    for (int sp = 0; sp < LOG2N2; sp += 3) {
        int half = 1 << sp;
        int pos  = tid & (half - 1);
        int base = ((tid >> sp) << (sp + 3)) | pos;
        float2 v[8];
        if (FHZ && sp == 0) {
            v[0] = s[SWZ(base + 0)];
            v[2] = s[SWZ(base + 2)];
            v[4] = s[SWZ(base + 4)];
            v[6] = s[SWZ(base + 6)];
            v[1] = v[0]; v[3] = v[2]; v[5] = v[4]; v[7] = v[6];
        } else {
#pragma unroll
            for (int q = 0; q < 8; ++q) v[q] = s[SWZ(base + q*half)];
            int stepA = NFFT >> (sp + 1);
            float2 wA = __ldg(&g_tw[pos*stepA]);
            bf2(v[0], v[1], wA, inv); bf2(v[2], v[3], wA, inv);
            bf2(v[4], v[5], wA, inv); bf2(v[6], v[7], wA, inv);
        }
        int stepB = NFFT >> (sp + 2);
        int stepC = NFFT >> (sp + 3);
        float2 wB0 = __ldg(&g_tw[pos*stepB]), wB1 = __ldg(&g_tw[(pos+half)*stepB]);
        bf2(v[0], v[2], wB0, inv); bf2(v[1], v[3], wB1, inv);
        bf2(v[4], v[6], wB0, inv); bf2(v[5], v[7], wB1, inv);
        float2 wC0 = __ldg(&g_tw[pos*stepC]),        wC1 = __ldg(&g_tw[(pos+half)*stepC]);
        float2 wC2 = __ldg(&g_tw[(pos+2*half)*stepC]), wC3 = __ldg(&g_tw[(pos+3*half)*stepC]);
        bf2(v[0], v[4], wC0, inv); bf2(v[1], v[5], wC1, inv);
        bf2(v[2], v[6], wC2, inv); bf2(v[3], v[7], wC3, inv);
#pragma unroll
        for (int q = 0; q < 8; ++q) s[SWZ(base + q*half)] = v[q];
        __syncthreads();
    }
}

#define SMEM_FFT (N2 * (int)sizeof(float2))   // 32 KB data only

__device__ __forceinline__ float2 ldcs2(const float2* p) {
    float2 r;
    asm volatile("ld.global.cs.v2.f32 {%0,%1}, [%2];" : "=f"(r.x), "=f"(r.y) : "l"(p));
    return r;
}

// -------- forward rfft of real rows (load straight into brev positions) ----
// mode 0: x rows from g_xt -> g_Xf ; mode 1: kernel rows -> g_Kf
__global__ __launch_bounds__(512) void k_fft_fwd(const float* __restrict__ kern, int mode) {
    float2* s = (float2*)dynsmem;
    int tid = threadIdx.x, bs = blockDim.x;
    size_t row = blockIdx.x;
    const float* src = mode ? (kern + row*L_) : (g_xt + row*L_);
    for (int m = tid; m < L_/2; m += bs)
        s[SWZ(BREV(m))] = ldcs2((const float2*)&src[2*m]);
    __syncthreads();
    block_fft<true>(s, tid, false);
    float2* dst = (mode ? g_Kf : g_Xf) + row*(size_t)N2;
    for (int k = tid; k < N2; k += bs) {
        if (k == 0) {
            float2 z0 = s[SWZ(0)];
            dst[0] = make_float2(z0.x + z0.y, z0.x - z0.y);
        } else {
            float2 A = s[SWZ(k)], Bm = s[SWZ(N2 - k)];
            float2 E = make_float2(0.5f*(A.x + Bm.x), 0.5f*(A.y - Bm.y));
            float2 O = make_float2(0.5f*(A.y + Bm.y), -0.5f*(A.x - Bm.x));
            float2 w = __ldg(&g_tw[k]);
            dst[k] = make_float2(E.x + w.x*O.x - w.y*O.y,
                                 E.y + w.x*O.y + w.y*O.x);
        }
    }
}

// ---- spectrum product (dmat folded: K' = K + dsc) fused with inverse
// Hermitian pack (brev scatter) + inverse FFT + bf16 split epilogue ----
// block decode: cd = idx>>1, bb = idx&1 (adjacent pair shares kf row)
__global__ __launch_bounds__(512) void k_conv_ifft(const float* __restrict__ dmat) {
    float2* s = (float2*)dynsmem;
    int tid = threadIdx.x, bs = blockDim.x;
    int idx = blockIdx.x;
    int cd = idx >> 1;
    int bb = idx & 1;
    int d  = cd & (D_-1);
    const float2* xf = g_Xf + ((size_t)(bb*D_ + d))*N2;
    const float2* kf = g_Kf + (size_t)cd*N2;
    float dsc = __ldg(&dmat[cd]);
    for (int k = tid; k < N2/2; k += bs) {
        if (k == 0) {
            float2 a0 = ldcs2(&xf[0]), b0 = __ldg(&kf[0]);
            float y0 = a0.x*(b0.x + dsc), yn = a0.y*(b0.y + dsc);
            s[SWZ(0)] = make_float2(0.5f*(y0 + yn), 0.5f*(y0 - yn));   // BREV(0)=0
            float2 ah = ldcs2(&xf[N2/2]), bh = __ldg(&kf[N2/2]);
            bh.x += dsc;
            float2 Yh = make_float2(ah.x*bh.x - ah.y*bh.y, ah.x*bh.y + ah.y*bh.x);
            s[SWZ(1)] = make_float2(Yh.x, -Yh.y);                       // BREV(N2/2)=1
        } else {
            float2 a  = ldcs2(&xf[k]),      b  = __ldg(&kf[k]);
            float2 a2 = ldcs2(&xf[N2 - k]), b2 = __ldg(&kf[N2 - k]);
            b.x += dsc; b2.x += dsc;
            float2 Yk = make_float2(a.x*b.x - a.y*b.y,   a.x*b.y + a.y*b.x);
            float2 Ym = make_float2(a2.x*b2.x - a2.y*b2.y, a2.x*b2.y + a2.y*b2.x);
            float2 E  = make_float2(0.5f*(Yk.x + Ym.x), 0.5f*(Yk.y - Ym.y));
            float2 Ow = make_float2(0.5f*(Yk.x - Ym.x), 0.5f*(Yk.y + Ym.y));
            float2 w = __ldg(&g_tw[k]);
            float2 O = make_float2(Ow.x*w.x + Ow.y*w.y, Ow.y*w.x - Ow.x*w.y);
            s[SWZ(BREV(k))]      = make_float2(E.x - O.y,  E.y + O.x);
            s[SWZ(BREV(N2 - k))] = make_float2(E.x + O.y, -E.y + O.x);
        }
    }
    __syncthreads();
    block_fft<false>(s, tid, true);
    size_t orow = (size_t)(bb*CD_ + cd)*L_;
    __nv_bfloat162* yh = (__nv_bfloat162*)(g_yh + orow);
    __nv_bfloat162* yl = (__nv_bfloat162*)(g_yl + orow);
    const float invn = 1.0f/(float)N2;
    for (int m = tid; m < L_/2; m += bs) {
        float2 z = s[SWZ(m)];
        float ox = z.x*invn;
        float oy = z.y*invn;
        __nv_bfloat16 h0 = __float2bfloat16(ox);
        __nv_bfloat16 h1 = __float2bfloat16(oy);
        __nv_bfloat16 l0 = __float2bfloat16(ox - __bfloat162float(h0));
        __nv_bfloat16 l1 = __float2bfloat16(oy - __bfloat162float(h1));
        __nv_bfloat162 hh; hh.x = h0; hh.y = h1;
        __nv_bfloat162 ll; ll.x = l0; ll.y = l1;
        yh[m] = hh;
        yl[m] = ll;
    }
}

// ======== mma.sync bf16 split GEMM machinery ========
#define KP 40   // smem row pitch (bf16): 32 data + 8 pad
#define BUFE (128*KP)            // elements per buffer
#define BUFB (BUFE*2)            // bytes per buffer
#define SM_MMA (2*4*BUFB)        // 2 stages x 4 buffers = 81920 B

__device__ __forceinline__ uint32_t smem_u32(const void* p) {
    uint32_t a;
    asm("{ .reg .u64 t; cvta.to.shared.u64 t, %1; cvt.u32.u64 %0, t; }" : "=r"(a) : "l"(p));
    return a;
}
__device__ __forceinline__ void cpa16(uint32_t saddr, const void* g) {
    asm volatile("cp.async.cg.shared.global [%0], [%1], 16;" :: "r"(saddr), "l"(g));
}
__device__ __forceinline__ void ldsm4(uint32_t& r0, uint32_t& r1, uint32_t& r2,
                                      uint32_t& r3, uint32_t addr) {
    asm volatile("ldmatrix.sync.aligned.m8n8.x4.shared.b16 {%0,%1,%2,%3}, [%4];"
                 : "=r"(r0), "=r"(r1), "=r"(r2), "=r"(r3) : "r"(addr));
}
__device__ __forceinline__ void ldsm4t(uint32_t& r0, uint32_t& r1, uint32_t& r2,
                                       uint32_t& r3, uint32_t addr) {
    asm volatile("ldmatrix.sync.aligned.m8n8.x4.trans.shared.b16 {%0,%1,%2,%3}, [%4];"
                 : "=r"(r0), "=r"(r1), "=r"(r2), "=r"(r3) : "r"(addr));
}
__device__ __forceinline__ void ldsm2(uint32_t& r0, uint32_t& r1, uint32_t addr) {
    asm volatile("ldmatrix.sync.aligned.m8n8.x2.shared.b16 {%0,%1}, [%2];"
                 : "=r"(r0), "=r"(r1) : "r"(addr));
}
__device__ __forceinline__ void mma16816(float* d, const uint32_t* a, const uint32_t* b) {
    asm volatile(
        "mma.sync.aligned.m16n8k16.row.col.f32.bf16.bf16.f32 "
        "{%0,%1,%2,%3}, {%4,%5,%6,%7}, {%8,%9}, {%0,%1,%2,%3};"
        : "+f"(d[0]), "+f"(d[1]), "+f"(d[2]), "+f"(d[3])
        : "r"(a[0]), "r"(a[1]), "r"(a[2]), "r"(a[3]), "r"(b[0]), "r"(b[1]));
}

// ======== k_mma_in: in_proj GEMM (A row-major [m][k]) ======
__global__ __launch_bounds__(256) void k_mma_in(const float* __restrict__ bias) {
    const int KDIM = D_;
    uint32_t sbase = smem_u32(dynsmem);
    int tid = threadIdx.x, wid = tid >> 5, lid = tid & 31;
    int n0 = blockIdx.x*128, m0 = blockIdx.y*128;
    int wm = wid & 3, wn = wid >> 2;

    float acc[2][8][4];
#pragma unroll
    for (int i = 0; i < 2; ++i)
#pragma unroll
        for (int j = 0; j < 8; ++j)
#pragma unroll
            for (int c = 0; c < 4; ++c) acc[i][j][c] = 0.f;

    int r0i = tid >> 2, c0i = tid & 3;
    int r1i = r0i + 64;
    const __nv_bfloat16* pA0h = g_ut_hi + (size_t)(m0 + r0i)*KDIM + c0i*8;
    const __nv_bfloat16* pA1h = g_ut_hi + (size_t)(m0 + r1i)*KDIM + c0i*8;
    const __nv_bfloat16* pA0l = g_ut_lo + (size_t)(m0 + r0i)*KDIM + c0i*8;
    const __nv_bfloat16* pA1l = g_ut_lo + (size_t)(m0 + r1i)*KDIM + c0i*8;
    const __nv_bfloat16* pB0h = g_w2_hi + (size_t)(n0 + r0i)*KDIM + c0i*8;
    const __nv_bfloat16* pB1h = g_w2_hi + (size_t)(n0 + r1i)*KDIM + c0i*8;
    const __nv_bfloat16* pB0l = g_w2_lo + (size_t)(n0 + r0i)*KDIM + c0i*8;
    const __nv_bfloat16* pB1l = g_w2_lo + (size_t)(n0 + r1i)*KDIM + c0i*8;
    uint32_t so0 = (r0i*KP + c0i*8)*2;
    uint32_t so1 = (r1i*KP + c0i*8)*2;

    const int NS = KDIM/32;

#define ISSUE_IN(s, stg) do {                                                 \
        int _k0 = (s)*32;                                                     \
        uint32_t _st = sbase + (stg)*4*BUFB;                                  \
        cpa16(_st + 0*BUFB + so0, pA0h + _k0);                                \
        cpa16(_st + 0*BUFB + so1, pA1h + _k0);                                \
        cpa16(_st + 1*BUFB + so0, pA0l + _k0);                                \
        cpa16(_st + 1*BUFB + so1, pA1l + _k0);                                \
        cpa16(_st + 2*BUFB + so0, pB0h + _k0);                                \
        cpa16(_st + 2*BUFB + so1, pB1h + _k0);                                \
        cpa16(_st + 3*BUFB + so0, pB0l + _k0);                                \
        cpa16(_st + 3*BUFB + so1, pB1l + _k0);                                \
        asm volatile("cp.async.commit_group;");                               \
    } while (0)

    ISSUE_IN(0, 0);

    for (int s = 0; s < NS; ++s) {
        if (s + 1 < NS) {
            ISSUE_IN(s + 1, (s + 1) & 1);
            asm volatile("cp.async.wait_group 1;");
        } else {
            asm volatile("cp.async.wait_group 0;");
        }
        __syncthreads();
        uint32_t soff = (uint32_t)(s & 1)*4*BUFB;
        uint32_t aAh = sbase + soff + 0*BUFB;
        uint32_t aAl = sbase + soff + 1*BUFB;
        uint32_t aBh = sbase + soff + 2*BUFB;
        uint32_t aBl = sbase + soff + 3*BUFB;
#pragma unroll
        for (int h = 0; h < 2; ++h) {
            int koff = h*16;
            uint32_t ah[2][4], al[2][4];
            {
                int mat = lid >> 3, rin = lid & 7;
                int arow = wm*32 + ((mat & 1) ? 8 : 0) + rin;
                int acol = koff + ((mat >> 1) ? 8 : 0);
#pragma unroll
                for (int mt = 0; mt < 2; ++mt) {
                    uint32_t off = ((arow + mt*16)*KP + acol)*2;
                    ldsm4(ah[mt][0], ah[mt][1], ah[mt][2], ah[mt][3], aAh + off);
                    ldsm4(al[mt][0], al[mt][1], al[mt][2], al[mt][3], aAl + off);
                }
            }
            {
                int mat = (lid >> 3) & 1, rin = lid & 7;
                int brow_base = wn*64 + rin;
                int bcol = koff + mat*8;
#pragma unroll
                for (int jt = 0; jt < 8; ++jt) {
                    uint32_t off = ((brow_base + jt*8)*KP + bcol)*2;
                    uint32_t bh[2], bl[2];
                    ldsm2(bh[0], bh[1], aBh + off);
                    ldsm2(bl[0], bl[1], aBl + off);
#pragma unroll
                    for (int mt = 0; mt < 2; ++mt) {
                        mma16816(acc[mt][jt], ah[mt], bh);
                        mma16816(acc[mt][jt], ah[mt], bl);
                        mma16816(acc[mt][jt], al[mt], bh);
                    }
                }
            }
        }
        __syncthreads();
    }
#undef ISSUE_IN

    int qr = lid >> 2, qc = lid & 3;
#pragma unroll
    for (int mt = 0; mt < 2; ++mt) {
#pragma unroll
        for (int jt = 0; jt < 8; ++jt) {
            int n = n0 + wn*64 + jt*8 + qc*2;
            int m_a = m0 + wm*32 + mt*16 + qr;
            int m_b = m_a + 8;
            float b0 = bias[n], b1 = bias[n+1];
            int ba = m_a >> 12, la = m_a & (L_-1);
            int bbv = m_b >> 12, lb = m_b & (L_-1);
            g_xt[((size_t)(ba*D_  + n  ))*L_ + la] = acc[mt][jt][0] + b0;
            g_xt[((size_t)(ba*D_  + n+1))*L_ + la] = acc[mt][jt][1] + b1;
            g_xt[((size_t)(bbv*D_ + n  ))*L_ + lb] = acc[mt][jt][2] + b0;
            g_xt[((size_t)(bbv*D_ + n+1))*L_ + lb] = acc[mt][jt][3] + b1;
        }
    }
}

// ======== k_mma_out: out_proj GEMM, A from [k][m] via ldmatrix.trans ========
#define KPA  136                 // A smem pitch (bf16): 128 data + 8 pad
#define ABUF (32*KPA*2)          // 8704 B per A buffer (32 k-rows x 128 m)
#define BBUF (128*KP*2)          // 10240 B per B buffer
#define STGB (2*ABUF + 2*BBUF)   // bytes per stage
#define SM_MO (2*STGB)           // 75776 B

__global__ __launch_bounds__(256) void k_mma_out(const float* __restrict__ outb,
                                                 float* __restrict__ out) {
    const int KDIM = CD_;
    uint32_t sbase = smem_u32(dynsmem);
    int tid = threadIdx.x, wid = tid >> 5, lid = tid & 31;
    int n0 = blockIdx.x*128, m0 = blockIdx.y*128;
    int wm = wid & 3, wn = wid >> 2;
    int bbm = m0 >> 12;                 // batch of this m-tile
    int l0  = m0 & (L_-1);

    float acc[2][8][4];
#pragma unroll
    for (int i = 0; i < 2; ++i)
#pragma unroll
        for (int j = 0; j < 8; ++j)
#pragma unroll
            for (int c = 0; c < 4; ++c) acc[i][j][c] = 0.f;

    // A: [k][m] rows; thread handles rows rA and rA+16, chunk cA
    int rA = tid >> 4, cA = tid & 15;
    const __nv_bfloat16* Ahb = g_yh + (size_t)bbm*CD_*L_ + l0;
    const __nv_bfloat16* Alb = g_yl + (size_t)bbm*CD_*L_ + l0;
    uint32_t soA0 = (rA*KPA + cA*8)*2;
    uint32_t soA1 = ((rA+16)*KPA + cA*8)*2;
    // B: [n][k] rows
    int r0i = tid >> 2, c0i = tid & 3;
    int r1i = r0i + 64;
    const __nv_bfloat16* pB0h = g_wt_hi + (size_t)(n0 + r0i)*KDIM + c0i*8;
    const __nv_bfloat16* pB1h = g_wt_hi + (size_t)(n0 + r1i)*KDIM + c0i*8;
    const __nv_bfloat16* pB0l = g_wt_lo + (size_t)(n0 + r0i)*KDIM + c0i*8;
    const __nv_bfloat16* pB1l = g_wt_lo + (size_t)(n0 + r1i)*KDIM + c0i*8;
    uint32_t soB0 = (r0i*KP + c0i*8)*2;
    uint32_t soB1 = (r1i*KP + c0i*8)*2;

    const int NS = KDIM/32;

#define ISSUE_OUT(s, stg) do {                                                \
        int _k0 = (s)*32;                                                     \
        uint32_t _st = sbase + (stg)*STGB;                                    \
        cpa16(_st + soA0,            Ahb + (size_t)(_k0 + rA)*L_ + cA*8);     \
        cpa16(_st + soA1,            Ahb + (size_t)(_k0 + rA + 16)*L_ + cA*8);\
        cpa16(_st + ABUF + soA0,     Alb + (size_t)(_k0 + rA)*L_ + cA*8);     \
        cpa16(_st + ABUF + soA1,     Alb + (size_t)(_k0 + rA + 16)*L_ + cA*8);\
        cpa16(_st + 2*ABUF + soB0,        pB0h + _k0);                        \
        cpa16(_st + 2*ABUF + soB1,        pB1h + _k0);                        \
        cpa16(_st + 2*ABUF + BBUF + soB0, pB0l + _k0);                        \
        cpa16(_st + 2*ABUF + BBUF + soB1, pB1l + _k0);                        \
        asm volatile("cp.async.commit_group;");                               \
    } while (0)

    ISSUE_OUT(0, 0);

    for (int s = 0; s < NS; ++s) {
        if (s + 1 < NS) {
            ISSUE_OUT(s + 1, (s + 1) & 1);
            asm volatile("cp.async.wait_group 1;");
        } else {
            asm volatile("cp.async.wait_group 0;");
        }
        __syncthreads();
        uint32_t soff = (uint32_t)(s & 1)*STGB;
        uint32_t aAh = sbase + soff;
        uint32_t aAl = sbase + soff + ABUF;
        uint32_t aBh = sbase + soff + 2*ABUF;
        uint32_t aBl = sbase + soff + 2*ABUF + BBUF;
#pragma unroll
        for (int h = 0; h < 2; ++h) {
            int koff = h*16;
            uint32_t ah[2][4], al[2][4];
            {
                int mat = lid >> 3, rin = lid & 7;
                int akrow = koff + ((mat >> 1) ? 8 : 0) + rin;
                int amcol = wm*32 + ((mat & 1) ? 8 : 0);
#pragma unroll
                for (int mt = 0; mt < 2; ++mt) {
                    uint32_t off = (akrow*KPA + amcol + mt*16)*2;
                    ldsm4t(ah[mt][0], ah[mt][1], ah[mt][2], ah[mt][3], aAh + off);
                    ldsm4t(al[mt][0], al[mt][1], al[mt][2], al[mt][3], aAl + off);
                }
            }
            {
                int mat = (lid >> 3) & 1, rin = lid & 7;
                int brow_base = wn*64 + rin;
                int bcol = koff + mat*8;
#pragma unroll
                for (int jt = 0; jt < 8; ++jt) {
                    uint32_t off = ((brow_base + jt*8)*KP + bcol)*2;
                    uint32_t bh[2], bl[2];
                    ldsm2(bh[0], bh[1], aBh + off);
                    ldsm2(bl[0], bl[1], aBl + off);
#pragma unroll
                    for (int mt = 0; mt < 2; ++mt) {
                        mma16816(acc[mt][jt], ah[mt], bh);
                        mma16816(acc[mt][jt], ah[mt], bl);
                        mma16816(acc[mt][jt], al[mt], bh);
                    }
                }
            }
        }
        __syncthreads();
    }
#undef ISSUE_OUT

    int qr = lid >> 2, qc = lid & 3;
#pragma unroll
    for (int mt = 0; mt < 2; ++mt) {
#pragma unroll
        for (int jt = 0; jt < 8; ++jt) {
            int n = n0 + wn*64 + jt*8 + qc*2;
            int m_a = m0 + wm*32 + mt*16 + qr;
            int m_b = m_a + 8;
            float b0 = outb[n], b1 = outb[n+1];
            int ba = m_a >> 12, la = m_a & (L_-1);
            int bbv = m_b >> 12, lb = m_b & (L_-1);
            float2 va = make_float2(acc[mt][jt][0] + b0, acc[mt][jt][1] + b1);
            float2 vb = make_float2(acc[mt][jt][2] + b0, acc[mt][jt][3] + b1);
            *(float2*)&out[((size_t)(ba*L_ + la))*D_ + n] = va;
            *(float2*)&out[((size_t)(bbv*L_ + lb))*D_ + n] = vb;
        }
    }
}

extern "C" void kernel_launch(void* const* d_in, const int* in_sizes, int n_in,
                              void* d_out, int out_size) {
    const float* u    = (const float*)d_in[0];
    const float* in_w = (const float*)d_in[1];
    const float* in_b = (const float*)d_in[2];
    const float* kern = (const float*)d_in[3];
    const float* dmat = (const float*)d_in[4];
    const float* outw = (const float*)d_in[5];
    const float* outb = (const float*)d_in[6];
    float* out = (float*)d_out;

    cudaFuncSetAttribute(k_fft_fwd,   cudaFuncAttributeMaxDynamicSharedMemorySize, SMEM_FFT);
    cudaFuncSetAttribute(k_conv_ifft, cudaFuncAttributeMaxDynamicSharedMemorySize, SMEM_FFT);
    cudaFuncSetAttribute(k_mma_out,   cudaFuncAttributeMaxDynamicSharedMemorySize, SM_MO);
    cudaFuncSetAttribute(k_mma_in,    cudaFuncAttributeMaxDynamicSharedMemorySize, SM_MMA);

    // fork root (side streams must first wait on an origin-stream event)
    cudaEventRecord(s_evRoot, 0);

    // side stream 2: out_w transpose (independent until k_mma_out)
    cudaStreamWaitEvent(s_str2, s_evRoot, 0);
    { dim3 g(CD_/32, D_/32); k_wtr<<<g, dim3(32,8), 0, s_str2>>>(outw); }
    cudaEventRecord(s_evW, s_str2);

    // main: twiddles, then fork kernel-rows FFT onto side stream 1
    k_tw<<<(NFFT/2 + 255)/256, 256>>>();
    cudaEventRecord(s_evTw, 0);
    cudaStreamWaitEvent(s_str1, s_evTw, 0);
    k_fft_fwd<<<C_*D_, 512, SMEM_FFT, s_str1>>>(kern, 1);   // kernel rows
    cudaEventRecord(s_evK, s_str1);

    // main chain: u split -> in_w transpose -> in_proj GEMM -> x-rows FFT
    k_usplit<<<(B_*L_*D_/2)/256, 256>>>(u);
    { dim3 g(D_/32, D_/32); k_w2tr<<<g, dim3(32,8)>>>(in_w); }
    { dim3 g(D_/128, (B_*L_)/128); k_mma_in<<<g, 256, SM_MMA>>>(in_b); }
    k_fft_fwd<<<B_*D_, 512, SMEM_FFT>>>(kern, 0);           // x rows

    // join: conv needs g_Kf (stream 1)
    cudaStreamWaitEvent(0, s_evK, 0);
    k_conv_ifft<<<B_*C_*D_, 512, SMEM_FFT>>>(dmat);

    // join: mma_out needs g_wt (stream 2)
    cudaStreamWaitEvent(0, s_evW, 0);
    { dim3 g(D_/128, (B_*L_)/128); k_mma_out<<<g, 256, SM_MO>>>(outb, out); }
}